// round 2
// baseline (speedup 1.0000x reference)
#include <cuda_runtime.h>

#define NN 30000
#define NE 480000
#define HID 128
#define F_IN 64
#define F_EDGE 16
#define NCLS 10

typedef unsigned long long ull;

__device__ __forceinline__ ull pack2(float lo, float hi) {
    ull r; asm("mov.b64 %0, {%1, %2};" : "=l"(r) : "f"(lo), "f"(hi)); return r;
}
__device__ __forceinline__ float2 unpack2(ull v) {
    float2 r; asm("mov.b64 {%0, %1}, %2;" : "=f"(r.x), "=f"(r.y) : "l"(v)); return r;
}
__device__ __forceinline__ void fma2(ull& d, ull a, ull b) {
    asm("fma.rn.f32x2 %0, %1, %2, %0;" : "+l"(d) : "l"(a), "l"(b));
}

// ---------------- device scratch ----------------
__device__ __align__(16) float g_ea[(size_t)NE * HID];   // dst-sorted edge encodings
__device__ int   g_perm[NE];
__device__ int   g_srcs[NE];
__device__ int   g_rowptr[NN + 1];
__device__ int   g_cnt[NN];
__device__ __align__(16) float g_h[NN * HID];
__device__ __align__(16) float g_nin[NN * HID];
__device__ __align__(16) float g_agg[NN * HID];
__device__ __align__(16) float g_mid[NN * 2 * HID];

// ---------------- CSR build ----------------
__global__ void k_zero_cnt() {
    int i = blockIdx.x * blockDim.x + threadIdx.x;
    if (i < NN) g_cnt[i] = 0;
}

__global__ void k_hist(const int* __restrict__ dst) {
    int i = blockIdx.x * blockDim.x + threadIdx.x;
    if (i < NE) atomicAdd(&g_cnt[dst[i]], 1);
}

// exclusive scan of g_cnt into g_rowptr; also resets g_cnt to 0
__global__ __launch_bounds__(1024) void k_scan() {
    __shared__ int wsum[32];
    const int CH = 30;
    int tid = threadIdx.x;
    int base = tid * CH;
    int loc[CH];
    int s = 0;
#pragma unroll
    for (int i = 0; i < CH; i++) {
        int idx = base + i;
        loc[i] = (idx < NN) ? g_cnt[idx] : 0;
        s += loc[i];
    }
    int lane = tid & 31, wid = tid >> 5;
    int v = s;
#pragma unroll
    for (int off = 1; off < 32; off <<= 1) {
        int t = __shfl_up_sync(0xffffffffu, v, off);
        if (lane >= off) v += t;
    }
    if (lane == 31) wsum[wid] = v;
    __syncthreads();
    if (wid == 0) {
        int wv = wsum[lane];
#pragma unroll
        for (int off = 1; off < 32; off <<= 1) {
            int t = __shfl_up_sync(0xffffffffu, wv, off);
            if (lane >= off) wv += t;
        }
        wsum[lane] = wv;
    }
    __syncthreads();
    int run = v - s + (wid ? wsum[wid - 1] : 0);
#pragma unroll
    for (int i = 0; i < CH; i++) {
        int idx = base + i;
        if (idx < NN) {
            g_rowptr[idx] = run;
            run += loc[i];
            g_cnt[idx] = 0;
        }
    }
    if (tid == 1023) g_rowptr[NN] = run;
}

__global__ void k_scatter(const int* __restrict__ dst) {
    int i = blockIdx.x * blockDim.x + threadIdx.x;
    if (i < NE) {
        int d = dst[i];
        int pos = g_rowptr[d] + atomicAdd(&g_cnt[d], 1);
        g_perm[pos] = i;
    }
}

// ---------------- edge encoder: tiled GEMM, 128 edges x 128 cols per block ----------------
__global__ __launch_bounds__(256) void k_edge_enc(
    const float* __restrict__ edge_attr, const int* __restrict__ src,
    const float* __restrict__ W, const float* __restrict__ bias)
{
    __shared__ ull sA2[128][17];                 // duplicate-packed attrs
    __shared__ __align__(16) float sW[F_EDGE][HID];
    __shared__ int sperm[128];
    int p0 = blockIdx.x * 128;
    int tid = threadIdx.x;
    for (int i = tid; i < F_EDGE * HID; i += 256) ((float*)sW)[i] = W[i];
    if (tid < 128) {
        int e = g_perm[p0 + tid];
        sperm[tid] = e;
        g_srcs[p0 + tid] = src[e];
    }
    __syncthreads();
#pragma unroll
    for (int i = 0; i < 8; i++) {
        int idx = tid + i * 256;
        int r = idx >> 4, k = idx & 15;
        float v = edge_attr[sperm[r] * F_EDGE + k];
        sA2[r][k] = pack2(v, v);
    }
    __syncthreads();
    int tx = tid & 31, ty = tid >> 5;
    float2 b0 = *(const float2*)&bias[2 * tx];
    float2 b1 = *(const float2*)&bias[2 * tx + 64];
    ull ib0 = pack2(b0.x, b0.y), ib1 = pack2(b1.x, b1.y);
    ull acc[16][2];
#pragma unroll
    for (int i = 0; i < 16; i++) { acc[i][0] = ib0; acc[i][1] = ib1; }
#pragma unroll
    for (int k = 0; k < F_EDGE; k++) {
        ull w0 = *(const ull*)&sW[k][2 * tx];
        ull w1 = *(const ull*)&sW[k][2 * tx + 64];
#pragma unroll
        for (int i = 0; i < 16; i++) {
            ull a = sA2[ty * 16 + i][k];
            fma2(acc[i][0], a, w0);
            fma2(acc[i][1], a, w1);
        }
    }
#pragma unroll
    for (int i = 0; i < 16; i++) {
        size_t p = p0 + ty * 16 + i;
        float2 v0 = unpack2(acc[i][0]);
        float2 v1 = unpack2(acc[i][1]);
        *(float2*)&g_ea[p * HID + 2 * tx] = v0;
        *(float2*)&g_ea[p * HID + 2 * tx + 64] = v1;
    }
}

// ---------------- node encoder: h0 = x @ W + b ----------------
__global__ __launch_bounds__(256) void k_node_enc(
    const float* __restrict__ x, const float* __restrict__ W, const float* __restrict__ bias)
{
    __shared__ __align__(16) float sW[F_IN * HID];
    __shared__ __align__(16) float sB[HID];
    for (int i = threadIdx.x; i < F_IN * HID; i += 256) sW[i] = W[i];
    if (threadIdx.x < HID) sB[threadIdx.x] = bias[threadIdx.x];
    __syncthreads();
    int lane = threadIdx.x & 31;
    int warp = (blockIdx.x * 256 + threadIdx.x) >> 5;
    int nw = gridDim.x * 8;
    float4 bv = ((float4*)sB)[lane];
    for (int n = warp; n < NN; n += nw) {
        float a0 = x[n * F_IN + lane];
        float a1 = x[n * F_IN + 32 + lane];
        float4 acc = bv;
#pragma unroll
        for (int k = 0; k < F_IN; k++) {
            float ak = __shfl_sync(0xffffffffu, (k < 32) ? a0 : a1, k & 31);
            float4 w = ((const float4*)(sW + k * HID))[lane];
            acc.x = fmaf(ak, w.x, acc.x);
            acc.y = fmaf(ak, w.y, acc.y);
            acc.z = fmaf(ak, w.z, acc.z);
            acc.w = fmaf(ak, w.w, acc.w);
        }
        ((float4*)g_h)[n * 32 + lane] = acc;
    }
}

// ---------------- pre-norm: nin = relu(LN(h, g, b)) ----------------
__global__ __launch_bounds__(256) void k_prenorm(const float* __restrict__ gmm,
                                                 const float* __restrict__ bb)
{
    int lane = threadIdx.x & 31;
    int n = (blockIdx.x * 256 + threadIdx.x) >> 5;
    if (n >= NN) return;
    float4 v = ((const float4*)g_h)[n * 32 + lane];
    float s = v.x + v.y + v.z + v.w;
    float q = v.x * v.x + v.y * v.y + v.z * v.z + v.w * v.w;
#pragma unroll
    for (int off = 16; off; off >>= 1) {
        s += __shfl_xor_sync(0xffffffffu, s, off);
        q += __shfl_xor_sync(0xffffffffu, q, off);
    }
    float m = s * (1.f / 128.f);
    float var = q * (1.f / 128.f) - m * m;
    float rstd = rsqrtf(var + 1e-5f);
    float4 g4 = ((const float4*)gmm)[lane];
    float4 b4 = ((const float4*)bb)[lane];
    float4 o;
    o.x = fmaxf((v.x - m) * rstd * g4.x + b4.x, 0.f);
    o.y = fmaxf((v.y - m) * rstd * g4.y + b4.y, 0.f);
    o.z = fmaxf((v.z - m) * rstd * g4.z + b4.z, 0.f);
    o.w = fmaxf((v.w - m) * rstd * g4.w + b4.w, 0.f);
    ((float4*)g_nin)[n * 32 + lane] = o;
}

// ---------------- edge aggregation: one-pass softmax, unroll-2 ----------------
__global__ __launch_bounds__(256) void k_edge_agg(int layer, const float* __restrict__ t_arr)
{
    int lane = threadIdx.x & 31;
    int n = (blockIdx.x * 256 + threadIdx.x) >> 5;
    if (n >= NN) return;
    const float4* nin4 = (const float4*)((layer == 0) ? g_h : g_nin);
    const float4* ea4 = (const float4*)g_ea;
    float tv = t_arr[layer];
    int p = g_rowptr[n], end = g_rowptr[n + 1];
    float4 sa = make_float4(0.f, 0.f, 0.f, 0.f), wa = sa;
    float4 sb = sa, wb = sa;
    for (; p + 2 <= end; p += 2) {
        int s0 = g_srcs[p], s1 = g_srcs[p + 1];
        float4 e0 = ea4[(size_t)p * 32 + lane];
        float4 e1 = ea4[(size_t)(p + 1) * 32 + lane];
        float4 h0 = nin4[s0 * 32 + lane];
        float4 h1 = nin4[s1 * 32 + lane];
        float m00 = fmaxf(h0.x + e0.x, 0.f) + 1e-7f;
        float m01 = fmaxf(h0.y + e0.y, 0.f) + 1e-7f;
        float m02 = fmaxf(h0.z + e0.z, 0.f) + 1e-7f;
        float m03 = fmaxf(h0.w + e0.w, 0.f) + 1e-7f;
        float m10 = fmaxf(h1.x + e1.x, 0.f) + 1e-7f;
        float m11 = fmaxf(h1.y + e1.y, 0.f) + 1e-7f;
        float m12 = fmaxf(h1.z + e1.z, 0.f) + 1e-7f;
        float m13 = fmaxf(h1.w + e1.w, 0.f) + 1e-7f;
        float x00 = __expf(m00 * tv), x01 = __expf(m01 * tv);
        float x02 = __expf(m02 * tv), x03 = __expf(m03 * tv);
        float x10 = __expf(m10 * tv), x11 = __expf(m11 * tv);
        float x12 = __expf(m12 * tv), x13 = __expf(m13 * tv);
        sa.x += x00; sa.y += x01; sa.z += x02; sa.w += x03;
        sb.x += x10; sb.y += x11; sb.z += x12; sb.w += x13;
        wa.x = fmaf(m00, x00, wa.x); wa.y = fmaf(m01, x01, wa.y);
        wa.z = fmaf(m02, x02, wa.z); wa.w = fmaf(m03, x03, wa.w);
        wb.x = fmaf(m10, x10, wb.x); wb.y = fmaf(m11, x11, wb.y);
        wb.z = fmaf(m12, x12, wb.z); wb.w = fmaf(m13, x13, wb.w);
    }
    if (p < end) {
        int s0 = g_srcs[p];
        float4 e0 = ea4[(size_t)p * 32 + lane];
        float4 h0 = nin4[s0 * 32 + lane];
        float m00 = fmaxf(h0.x + e0.x, 0.f) + 1e-7f;
        float m01 = fmaxf(h0.y + e0.y, 0.f) + 1e-7f;
        float m02 = fmaxf(h0.z + e0.z, 0.f) + 1e-7f;
        float m03 = fmaxf(h0.w + e0.w, 0.f) + 1e-7f;
        float x00 = __expf(m00 * tv), x01 = __expf(m01 * tv);
        float x02 = __expf(m02 * tv), x03 = __expf(m03 * tv);
        sa.x += x00; sa.y += x01; sa.z += x02; sa.w += x03;
        wa.x = fmaf(m00, x00, wa.x); wa.y = fmaf(m01, x01, wa.y);
        wa.z = fmaf(m02, x02, wa.z); wa.w = fmaf(m03, x03, wa.w);
    }
    sa.x += sb.x; sa.y += sb.y; sa.z += sb.z; sa.w += sb.w;
    wa.x += wb.x; wa.y += wb.y; wa.z += wb.z; wa.w += wb.w;
    float4 o;
    o.x = wa.x / (sa.x + 1e-16f);
    o.y = wa.y / (sa.y + 1e-16f);
    o.z = wa.z / (sa.z + 1e-16f);
    o.w = wa.w / (sa.w + 1e-16f);
    ((float4*)g_agg)[n * 32 + lane] = o;
}

// ---------------- GEMM1: mid = relu(LN((agg+nin) @ W1 + b1)), 64x256 tile, f32x2 ----------------
__global__ __launch_bounds__(256) void k_gemm1(
    int layer, const float* __restrict__ W, const float* __restrict__ b,
    const float* __restrict__ lg, const float* __restrict__ lb)
{
    __shared__ ull sA2[64][33];
    __shared__ __align__(16) float sW[32][256];
    const float* nin = (layer == 0) ? g_h : g_nin;
    int tx = threadIdx.x & 31, ty = threadIdx.x >> 5;
    int row0 = blockIdx.x * 64;
    ull acc[8][4];
#pragma unroll
    for (int i = 0; i < 8; i++)
#pragma unroll
        for (int jp = 0; jp < 4; jp++) acc[i][jp] = 0ull;

    for (int kc = 0; kc < HID; kc += 32) {
#pragma unroll
        for (int i = 0; i < 8; i++) {
            int idx = threadIdx.x + i * 256;
            int r = idx >> 5, k = idx & 31;
            int n = row0 + r;
            float v = 0.f;
            if (n < NN) v = g_agg[n * HID + kc + k] + nin[n * HID + kc + k];
            sA2[r][k] = pack2(v, v);
        }
#pragma unroll
        for (int i = 0; i < 8; i++) {
            int idx = threadIdx.x + i * 256;
            int kk = idx >> 6, c4 = idx & 63;
            ((float4*)sW[kk])[c4] = ((const float4*)(W + (kc + kk) * 256))[c4];
        }
        __syncthreads();
#pragma unroll 8
        for (int k = 0; k < 32; k++) {
            ull a[8];
#pragma unroll
            for (int i = 0; i < 8; i++) a[i] = sA2[ty * 8 + i][k];
            ull w[4];
#pragma unroll
            for (int jp = 0; jp < 4; jp++) w[jp] = *(const ull*)&sW[k][2 * tx + 64 * jp];
#pragma unroll
            for (int i = 0; i < 8; i++)
#pragma unroll
                for (int jp = 0; jp < 4; jp++) fma2(acc[i][jp], a[i], w[jp]);
        }
        __syncthreads();
    }
    float2 bias[4], gg[4], bb2[4];
#pragma unroll
    for (int jp = 0; jp < 4; jp++) {
        int c = 2 * tx + 64 * jp;
        bias[jp] = *(const float2*)&b[c];
        gg[jp]   = *(const float2*)&lg[c];
        bb2[jp]  = *(const float2*)&lb[c];
    }
#pragma unroll
    for (int i = 0; i < 8; i++) {
        float2 v[4];
        float sum = 0.f, sq = 0.f;
#pragma unroll
        for (int jp = 0; jp < 4; jp++) {
            v[jp] = unpack2(acc[i][jp]);
            v[jp].x += bias[jp].x; v[jp].y += bias[jp].y;
            sum += v[jp].x + v[jp].y;
            sq = fmaf(v[jp].x, v[jp].x, sq);
            sq = fmaf(v[jp].y, v[jp].y, sq);
        }
#pragma unroll
        for (int off = 16; off; off >>= 1) {
            sum += __shfl_xor_sync(0xffffffffu, sum, off);
            sq += __shfl_xor_sync(0xffffffffu, sq, off);
        }
        float m = sum * (1.f / 256.f);
        float var = sq * (1.f / 256.f) - m * m;
        float rstd = rsqrtf(var + 1e-5f);
        int n = row0 + ty * 8 + i;
        if (n < NN) {
#pragma unroll
            for (int jp = 0; jp < 4; jp++) {
                float2 o;
                o.x = fmaxf((v[jp].x - m) * rstd * gg[jp].x + bb2[jp].x, 0.f);
                o.y = fmaxf((v[jp].y - m) * rstd * gg[jp].y + bb2[jp].y, 0.f);
                *(float2*)&g_mid[n * 256 + 2 * tx + 64 * jp] = o;
            }
        }
    }
}

// ---------------- GEMM2: h = mid @ W2 + b2 (+res), 128x128 tile, f32x2 ----------------
__global__ __launch_bounds__(256) void k_gemm2(
    const float* __restrict__ W, const float* __restrict__ b, int use_res)
{
    __shared__ ull sA2[128][33];
    __shared__ __align__(16) float sW[32][128];
    int tx = threadIdx.x & 31, ty = threadIdx.x >> 5;
    int row0 = blockIdx.x * 128;
    ull acc[16][2];
#pragma unroll
    for (int i = 0; i < 16; i++) { acc[i][0] = 0ull; acc[i][1] = 0ull; }

    for (int kc = 0; kc < 256; kc += 32) {
#pragma unroll
        for (int i = 0; i < 16; i++) {
            int idx = threadIdx.x + i * 256;
            int r = idx >> 5, k = idx & 31;
            int n = row0 + r;
            float v = (n < NN) ? g_mid[n * 256 + kc + k] : 0.f;
            sA2[r][k] = pack2(v, v);
        }
#pragma unroll
        for (int i = 0; i < 4; i++) {
            int idx = threadIdx.x + i * 256;
            int kk = idx >> 5, c4 = idx & 31;
            ((float4*)sW[kk])[c4] = ((const float4*)(W + (kc + kk) * 128))[c4];
        }
        __syncthreads();
#pragma unroll 4
        for (int k = 0; k < 32; k++) {
            ull w0 = *(const ull*)&sW[k][2 * tx];
            ull w1 = *(const ull*)&sW[k][2 * tx + 64];
#pragma unroll
            for (int i = 0; i < 16; i++) {
                ull a = sA2[ty * 16 + i][k];
                fma2(acc[i][0], a, w0);
                fma2(acc[i][1], a, w1);
            }
        }
        __syncthreads();
    }
    float2 b0 = *(const float2*)&b[2 * tx];
    float2 b1 = *(const float2*)&b[2 * tx + 64];
#pragma unroll
    for (int i = 0; i < 16; i++) {
        int n = row0 + ty * 16 + i;
        if (n < NN) {
            float2 v0 = unpack2(acc[i][0]);
            float2 v1 = unpack2(acc[i][1]);
            v0.x += b0.x; v0.y += b0.y;
            v1.x += b1.x; v1.y += b1.y;
            if (use_res) {
                float2 r0 = *(const float2*)&g_h[n * HID + 2 * tx];
                float2 r1 = *(const float2*)&g_h[n * HID + 2 * tx + 64];
                v0.x += r0.x; v0.y += r0.y;
                v1.x += r1.x; v1.y += r1.y;
            }
            *(float2*)&g_h[n * HID + 2 * tx] = v0;
            *(float2*)&g_h[n * HID + 2 * tx + 64] = v1;
        }
    }
}

// ---------------- classifier ----------------
__global__ __launch_bounds__(256) void k_classifier(
    const float* __restrict__ gmm, const float* __restrict__ bb,
    const float* __restrict__ lw, const float* __restrict__ lbias,
    float* __restrict__ out)
{
    int lane = threadIdx.x & 31;
    int n = (blockIdx.x * 256 + threadIdx.x) >> 5;
    if (n >= NN) return;
    float4 v = ((const float4*)g_h)[n * 32 + lane];
    float s = v.x + v.y + v.z + v.w;
    float q = v.x * v.x + v.y * v.y + v.z * v.z + v.w * v.w;
#pragma unroll
    for (int off = 16; off; off >>= 1) {
        s += __shfl_xor_sync(0xffffffffu, s, off);
        q += __shfl_xor_sync(0xffffffffu, q, off);
    }
    float m = s * (1.f / 128.f);
    float var = q * (1.f / 128.f) - m * m;
    float rstd = rsqrtf(var + 1e-5f);
    float4 g4 = ((const float4*)gmm)[lane];
    float4 b4 = ((const float4*)bb)[lane];
    float h0 = fmaxf((v.x - m) * rstd * g4.x + b4.x, 0.f);
    float h1 = fmaxf((v.y - m) * rstd * g4.y + b4.y, 0.f);
    float h2 = fmaxf((v.z - m) * rstd * g4.z + b4.z, 0.f);
    float h3 = fmaxf((v.w - m) * rstd * g4.w + b4.w, 0.f);
    int c0 = lane * 4;
    float r[NCLS];
#pragma unroll
    for (int j = 0; j < NCLS; j++) {
        float p = h0 * lw[c0 * NCLS + j];
        p = fmaf(h1, lw[(c0 + 1) * NCLS + j], p);
        p = fmaf(h2, lw[(c0 + 2) * NCLS + j], p);
        p = fmaf(h3, lw[(c0 + 3) * NCLS + j], p);
#pragma unroll
        for (int off = 16; off; off >>= 1) p += __shfl_xor_sync(0xffffffffu, p, off);
        r[j] = p;
    }
#pragma unroll
    for (int j = 0; j < NCLS; j++)
        if (lane == j) out[n * NCLS + j] = r[j] + lbias[j];
}

// ---------------- launch ----------------
extern "C" void kernel_launch(void* const* d_in, const int* in_sizes, int n_in,
                              void* d_out, int out_size)
{
    const float* x         = (const float*)d_in[0];
    const float* edge_attr = (const float*)d_in[1];
    const float* node_w    = (const float*)d_in[2];
    const float* node_b    = (const float*)d_in[3];
    const float* edge_w    = (const float*)d_in[4];
    const float* edge_b    = (const float*)d_in[5];
    const float* mlp1_w    = (const float*)d_in[6];
    const float* mlp1_b    = (const float*)d_in[7];
    const float* ln_g      = (const float*)d_in[8];
    const float* ln_b      = (const float*)d_in[9];
    const float* mlp2_w    = (const float*)d_in[10];
    const float* mlp2_b    = (const float*)d_in[11];
    const float* t         = (const float*)d_in[12];
    const float* norm_g    = (const float*)d_in[13];
    const float* norm_b    = (const float*)d_in[14];
    const float* lin_w     = (const float*)d_in[15];
    const float* lin_b     = (const float*)d_in[16];
    const int*   edge_index= (const int*)d_in[17];
    const int* src = edge_index;
    const int* dst = edge_index + NE;
    float* out = (float*)d_out;

    k_zero_cnt<<<(NN + 255) / 256, 256>>>();
    k_hist<<<(NE + 255) / 256, 256>>>(dst);
    k_scan<<<1, 1024>>>();
    k_scatter<<<(NE + 255) / 256, 256>>>(dst);

    k_edge_enc<<<NE / 128, 256>>>(edge_attr, src, edge_w, edge_b);
    k_node_enc<<<1184, 256>>>(x, node_w, node_b);

    for (int l = 0; l < 3; l++) {
        if (l > 0)
            k_prenorm<<<(NN * 32 + 255) / 256, 256>>>(norm_g + l * HID, norm_b + l * HID);
        k_edge_agg<<<(NN * 32 + 255) / 256, 256>>>(l, t);
        k_gemm1<<<(NN + 63) / 64, 256>>>(l, mlp1_w + l * HID * 2 * HID, mlp1_b + l * 2 * HID,
                                         ln_g + l * 2 * HID, ln_b + l * 2 * HID);
        k_gemm2<<<(NN + 127) / 128, 256>>>(mlp2_w + l * 2 * HID * HID, mlp2_b + l * HID, l > 0);
    }
    k_classifier<<<(NN * 32 + 255) / 256, 256>>>(norm_g, norm_b, lin_w, lin_b, out);
}

// round 3
// speedup vs baseline: 1.0631x; 1.0631x over previous
#include <cuda_runtime.h>
#include <cuda_fp16.h>

#define NN 30000
#define NE 480000
#define HID 128
#define F_IN 64
#define F_EDGE 16
#define NCLS 10

typedef unsigned long long ull;

__device__ __forceinline__ ull pack2(float lo, float hi) {
    ull r; asm("mov.b64 %0, {%1, %2};" : "=l"(r) : "f"(lo), "f"(hi)); return r;
}
__device__ __forceinline__ float2 unpack2(ull v) {
    float2 r; asm("mov.b64 {%0, %1}, %2;" : "=f"(r.x), "=f"(r.y) : "l"(v)); return r;
}
__device__ __forceinline__ void fma2(ull& d, ull a, ull b) {
    asm("fma.rn.f32x2 %0, %1, %2, %0;" : "+l"(d) : "l"(a), "l"(b));
}

// ---------------- device scratch ----------------
__device__ __align__(16) __half g_eah[(size_t)NE * HID];  // dst-sorted edge encodings, fp16 (122.9 MB)
__device__ int   g_perm[NE];
__device__ int   g_srcs[NE];
__device__ int   g_rowptr[NN + 1];
__device__ int   g_cnt[NN];
__device__ __align__(16) float g_h[NN * HID];
__device__ __align__(16) float g_nin[NN * HID];
__device__ __align__(16) float g_agg[NN * HID];
__device__ __align__(16) float g_mid[NN * 2 * HID];

// ---------------- CSR build ----------------
__global__ void k_zero_cnt() {
    int i = blockIdx.x * blockDim.x + threadIdx.x;
    if (i < NN) g_cnt[i] = 0;
}

__global__ void k_hist(const int* __restrict__ dst) {
    int i = blockIdx.x * blockDim.x + threadIdx.x;
    if (i < NE) atomicAdd(&g_cnt[dst[i]], 1);
}

__global__ __launch_bounds__(1024) void k_scan() {
    __shared__ int wsum[32];
    const int CH = 30;
    int tid = threadIdx.x;
    int base = tid * CH;
    int loc[CH];
    int s = 0;
#pragma unroll
    for (int i = 0; i < CH; i++) {
        int idx = base + i;
        loc[i] = (idx < NN) ? g_cnt[idx] : 0;
        s += loc[i];
    }
    int lane = tid & 31, wid = tid >> 5;
    int v = s;
#pragma unroll
    for (int off = 1; off < 32; off <<= 1) {
        int t = __shfl_up_sync(0xffffffffu, v, off);
        if (lane >= off) v += t;
    }
    if (lane == 31) wsum[wid] = v;
    __syncthreads();
    if (wid == 0) {
        int wv = wsum[lane];
#pragma unroll
        for (int off = 1; off < 32; off <<= 1) {
            int t = __shfl_up_sync(0xffffffffu, wv, off);
            if (lane >= off) wv += t;
        }
        wsum[lane] = wv;
    }
    __syncthreads();
    int run = v - s + (wid ? wsum[wid - 1] : 0);
#pragma unroll
    for (int i = 0; i < CH; i++) {
        int idx = base + i;
        if (idx < NN) {
            g_rowptr[idx] = run;
            run += loc[i];
            g_cnt[idx] = 0;
        }
    }
    if (tid == 1023) g_rowptr[NN] = run;
}

__global__ void k_scatter(const int* __restrict__ dst) {
    int i = blockIdx.x * blockDim.x + threadIdx.x;
    if (i < NE) {
        int d = dst[i];
        int pos = g_rowptr[d] + atomicAdd(&g_cnt[d], 1);
        g_perm[pos] = i;
    }
}

// ---------------- edge encoder: tiled GEMM -> fp16 output ----------------
__global__ __launch_bounds__(256) void k_edge_enc(
    const float* __restrict__ edge_attr, const int* __restrict__ src,
    const float* __restrict__ W, const float* __restrict__ bias)
{
    __shared__ ull sA2[128][17];
    __shared__ __align__(16) float sW[F_EDGE][HID];
    __shared__ int sperm[128];
    int p0 = blockIdx.x * 128;
    int tid = threadIdx.x;
    for (int i = tid; i < F_EDGE * HID; i += 256) ((float*)sW)[i] = W[i];
    if (tid < 128) {
        int e = g_perm[p0 + tid];
        sperm[tid] = e;
        g_srcs[p0 + tid] = src[e];
    }
    __syncthreads();
#pragma unroll
    for (int i = 0; i < 8; i++) {
        int idx = tid + i * 256;
        int r = idx >> 4, k = idx & 15;
        float v = edge_attr[sperm[r] * F_EDGE + k];
        sA2[r][k] = pack2(v, v);
    }
    __syncthreads();
    int tx = tid & 31, ty = tid >> 5;
    float2 b0 = *(const float2*)&bias[2 * tx];
    float2 b1 = *(const float2*)&bias[2 * tx + 64];
    ull ib0 = pack2(b0.x, b0.y), ib1 = pack2(b1.x, b1.y);
    ull acc[16][2];
#pragma unroll
    for (int i = 0; i < 16; i++) { acc[i][0] = ib0; acc[i][1] = ib1; }
#pragma unroll
    for (int k = 0; k < F_EDGE; k++) {
        ull w0 = *(const ull*)&sW[k][2 * tx];
        ull w1 = *(const ull*)&sW[k][2 * tx + 64];
#pragma unroll
        for (int i = 0; i < 16; i++) {
            ull a = sA2[ty * 16 + i][k];
            fma2(acc[i][0], a, w0);
            fma2(acc[i][1], a, w1);
        }
    }
#pragma unroll
    for (int i = 0; i < 16; i++) {
        size_t p = p0 + ty * 16 + i;
        float2 v0 = unpack2(acc[i][0]);
        float2 v1 = unpack2(acc[i][1]);
        *(__half2*)&g_eah[p * HID + 2 * tx]      = __float22half2_rn(v0);
        *(__half2*)&g_eah[p * HID + 2 * tx + 64] = __float22half2_rn(v1);
    }
}

// ---------------- node encoder ----------------
__global__ __launch_bounds__(256) void k_node_enc(
    const float* __restrict__ x, const float* __restrict__ W, const float* __restrict__ bias)
{
    __shared__ __align__(16) float sW[F_IN * HID];
    __shared__ __align__(16) float sB[HID];
    for (int i = threadIdx.x; i < F_IN * HID; i += 256) sW[i] = W[i];
    if (threadIdx.x < HID) sB[threadIdx.x] = bias[threadIdx.x];
    __syncthreads();
    int lane = threadIdx.x & 31;
    int warp = (blockIdx.x * 256 + threadIdx.x) >> 5;
    int nw = gridDim.x * 8;
    float4 bv = ((float4*)sB)[lane];
    for (int n = warp; n < NN; n += nw) {
        float a0 = x[n * F_IN + lane];
        float a1 = x[n * F_IN + 32 + lane];
        float4 acc = bv;
#pragma unroll
        for (int k = 0; k < F_IN; k++) {
            float ak = __shfl_sync(0xffffffffu, (k < 32) ? a0 : a1, k & 31);
            float4 w = ((const float4*)(sW + k * HID))[lane];
            acc.x = fmaf(ak, w.x, acc.x);
            acc.y = fmaf(ak, w.y, acc.y);
            acc.z = fmaf(ak, w.z, acc.z);
            acc.w = fmaf(ak, w.w, acc.w);
        }
        ((float4*)g_h)[n * 32 + lane] = acc;
    }
}

// ---------------- pre-norm ----------------
__global__ __launch_bounds__(256) void k_prenorm(const float* __restrict__ gmm,
                                                 const float* __restrict__ bb)
{
    int lane = threadIdx.x & 31;
    int n = (blockIdx.x * 256 + threadIdx.x) >> 5;
    if (n >= NN) return;
    float4 v = ((const float4*)g_h)[n * 32 + lane];
    float s = v.x + v.y + v.z + v.w;
    float q = v.x * v.x + v.y * v.y + v.z * v.z + v.w * v.w;
#pragma unroll
    for (int off = 16; off; off >>= 1) {
        s += __shfl_xor_sync(0xffffffffu, s, off);
        q += __shfl_xor_sync(0xffffffffu, q, off);
    }
    float m = s * (1.f / 128.f);
    float var = q * (1.f / 128.f) - m * m;
    float rstd = rsqrtf(var + 1e-5f);
    float4 g4 = ((const float4*)gmm)[lane];
    float4 b4 = ((const float4*)bb)[lane];
    float4 o;
    o.x = fmaxf((v.x - m) * rstd * g4.x + b4.x, 0.f);
    o.y = fmaxf((v.y - m) * rstd * g4.y + b4.y, 0.f);
    o.z = fmaxf((v.z - m) * rstd * g4.z + b4.z, 0.f);
    o.w = fmaxf((v.w - m) * rstd * g4.w + b4.w, 0.f);
    ((float4*)g_nin)[n * 32 + lane] = o;
}

// ---------------- edge aggregation: fp16 ea, unroll-4, batched loads ----------------
__device__ __forceinline__ float4 load_ea(size_t p, int lane) {
    uint2 raw = *(const uint2*)(g_eah + p * HID + lane * 4);
    float2 fa = __half22float2(*(__half2*)&raw.x);
    float2 fb = __half22float2(*(__half2*)&raw.y);
    return make_float4(fa.x, fa.y, fb.x, fb.y);
}

__global__ __launch_bounds__(256) void k_edge_agg(int layer, const float* __restrict__ t_arr)
{
    int lane = threadIdx.x & 31;
    int n = (blockIdx.x * 256 + threadIdx.x) >> 5;
    if (n >= NN) return;
    const float4* nin4 = (const float4*)((layer == 0) ? g_h : g_nin);
    float tv = t_arr[layer];
    int p = g_rowptr[n], end = g_rowptr[n + 1];
    float4 sa = make_float4(0.f, 0.f, 0.f, 0.f), wa = sa;
    float4 sb = sa, wb = sa;
    for (; p + 4 <= end; p += 4) {
        int s0 = g_srcs[p], s1 = g_srcs[p + 1], s2 = g_srcs[p + 2], s3 = g_srcs[p + 3];
        float4 e0 = load_ea(p, lane);
        float4 e1 = load_ea(p + 1, lane);
        float4 e2 = load_ea(p + 2, lane);
        float4 e3 = load_ea(p + 3, lane);
        float4 h0 = nin4[s0 * 32 + lane];
        float4 h1 = nin4[s1 * 32 + lane];
        float4 h2 = nin4[s2 * 32 + lane];
        float4 h3 = nin4[s3 * 32 + lane];
#define DO_EDGE(hh, ee, S, W) { \
        float m0 = fmaxf(hh.x + ee.x, 0.f) + 1e-7f; \
        float m1 = fmaxf(hh.y + ee.y, 0.f) + 1e-7f; \
        float m2 = fmaxf(hh.z + ee.z, 0.f) + 1e-7f; \
        float m3 = fmaxf(hh.w + ee.w, 0.f) + 1e-7f; \
        float x0 = __expf(m0 * tv), x1 = __expf(m1 * tv); \
        float x2 = __expf(m2 * tv), x3 = __expf(m3 * tv); \
        S.x += x0; S.y += x1; S.z += x2; S.w += x3; \
        W.x = fmaf(m0, x0, W.x); W.y = fmaf(m1, x1, W.y); \
        W.z = fmaf(m2, x2, W.z); W.w = fmaf(m3, x3, W.w); }
        DO_EDGE(h0, e0, sa, wa);
        DO_EDGE(h1, e1, sb, wb);
        DO_EDGE(h2, e2, sa, wa);
        DO_EDGE(h3, e3, sb, wb);
    }
    for (; p < end; p++) {
        int s0 = g_srcs[p];
        float4 e0 = load_ea(p, lane);
        float4 h0 = nin4[s0 * 32 + lane];
        DO_EDGE(h0, e0, sa, wa);
    }
#undef DO_EDGE
    sa.x += sb.x; sa.y += sb.y; sa.z += sb.z; sa.w += sb.w;
    wa.x += wb.x; wa.y += wb.y; wa.z += wb.z; wa.w += wb.w;
    float4 o;
    o.x = wa.x / (sa.x + 1e-16f);
    o.y = wa.y / (sa.y + 1e-16f);
    o.z = wa.z / (sa.z + 1e-16f);
    o.w = wa.w / (sa.w + 1e-16f);
    ((float4*)g_agg)[n * 32 + lane] = o;
}

// ---------------- GEMM1: 64x256 tile, f32x2 ----------------
__global__ __launch_bounds__(256) void k_gemm1(
    int layer, const float* __restrict__ W, const float* __restrict__ b,
    const float* __restrict__ lg, const float* __restrict__ lb)
{
    __shared__ ull sA2[64][33];
    __shared__ __align__(16) float sW[32][256];
    const float* nin = (layer == 0) ? g_h : g_nin;
    int tx = threadIdx.x & 31, ty = threadIdx.x >> 5;
    int row0 = blockIdx.x * 64;
    ull acc[8][4];
#pragma unroll
    for (int i = 0; i < 8; i++)
#pragma unroll
        for (int jp = 0; jp < 4; jp++) acc[i][jp] = 0ull;

    for (int kc = 0; kc < HID; kc += 32) {
#pragma unroll
        for (int i = 0; i < 8; i++) {
            int idx = threadIdx.x + i * 256;
            int r = idx >> 5, k = idx & 31;
            int n = row0 + r;
            float v = 0.f;
            if (n < NN) v = g_agg[n * HID + kc + k] + nin[n * HID + kc + k];
            sA2[r][k] = pack2(v, v);
        }
#pragma unroll
        for (int i = 0; i < 8; i++) {
            int idx = threadIdx.x + i * 256;
            int kk = idx >> 6, c4 = idx & 63;
            ((float4*)sW[kk])[c4] = ((const float4*)(W + (kc + kk) * 256))[c4];
        }
        __syncthreads();
#pragma unroll 8
        for (int k = 0; k < 32; k++) {
            ull a[8];
#pragma unroll
            for (int i = 0; i < 8; i++) a[i] = sA2[ty * 8 + i][k];
            ull w[4];
#pragma unroll
            for (int jp = 0; jp < 4; jp++) w[jp] = *(const ull*)&sW[k][2 * tx + 64 * jp];
#pragma unroll
            for (int i = 0; i < 8; i++)
#pragma unroll
                for (int jp = 0; jp < 4; jp++) fma2(acc[i][jp], a[i], w[jp]);
        }
        __syncthreads();
    }
    float2 bias[4], gg[4], bb2[4];
#pragma unroll
    for (int jp = 0; jp < 4; jp++) {
        int c = 2 * tx + 64 * jp;
        bias[jp] = *(const float2*)&b[c];
        gg[jp]   = *(const float2*)&lg[c];
        bb2[jp]  = *(const float2*)&lb[c];
    }
#pragma unroll
    for (int i = 0; i < 8; i++) {
        float2 v[4];
        float sum = 0.f, sq = 0.f;
#pragma unroll
        for (int jp = 0; jp < 4; jp++) {
            v[jp] = unpack2(acc[i][jp]);
            v[jp].x += bias[jp].x; v[jp].y += bias[jp].y;
            sum += v[jp].x + v[jp].y;
            sq = fmaf(v[jp].x, v[jp].x, sq);
            sq = fmaf(v[jp].y, v[jp].y, sq);
        }
#pragma unroll
        for (int off = 16; off; off >>= 1) {
            sum += __shfl_xor_sync(0xffffffffu, sum, off);
            sq += __shfl_xor_sync(0xffffffffu, sq, off);
        }
        float m = sum * (1.f / 256.f);
        float var = sq * (1.f / 256.f) - m * m;
        float rstd = rsqrtf(var + 1e-5f);
        int n = row0 + ty * 8 + i;
        if (n < NN) {
#pragma unroll
            for (int jp = 0; jp < 4; jp++) {
                float2 o;
                o.x = fmaxf((v[jp].x - m) * rstd * gg[jp].x + bb2[jp].x, 0.f);
                o.y = fmaxf((v[jp].y - m) * rstd * gg[jp].y + bb2[jp].y, 0.f);
                *(float2*)&g_mid[n * 256 + 2 * tx + 64 * jp] = o;
            }
        }
    }
}

// ---------------- GEMM2: 128x128 tile, f32x2 ----------------
__global__ __launch_bounds__(256) void k_gemm2(
    const float* __restrict__ W, const float* __restrict__ b, int use_res)
{
    __shared__ ull sA2[128][33];
    __shared__ __align__(16) float sW[32][128];
    int tx = threadIdx.x & 31, ty = threadIdx.x >> 5;
    int row0 = blockIdx.x * 128;
    ull acc[16][2];
#pragma unroll
    for (int i = 0; i < 16; i++) { acc[i][0] = 0ull; acc[i][1] = 0ull; }

    for (int kc = 0; kc < 256; kc += 32) {
#pragma unroll
        for (int i = 0; i < 16; i++) {
            int idx = threadIdx.x + i * 256;
            int r = idx >> 5, k = idx & 31;
            int n = row0 + r;
            float v = (n < NN) ? g_mid[n * 256 + kc + k] : 0.f;
            sA2[r][k] = pack2(v, v);
        }
#pragma unroll
        for (int i = 0; i < 4; i++) {
            int idx = threadIdx.x + i * 256;
            int kk = idx >> 5, c4 = idx & 31;
            ((float4*)sW[kk])[c4] = ((const float4*)(W + (kc + kk) * 128))[c4];
        }
        __syncthreads();
#pragma unroll 4
        for (int k = 0; k < 32; k++) {
            ull w0 = *(const ull*)&sW[k][2 * tx];
            ull w1 = *(const ull*)&sW[k][2 * tx + 64];
#pragma unroll
            for (int i = 0; i < 16; i++) {
                ull a = sA2[ty * 16 + i][k];
                fma2(acc[i][0], a, w0);
                fma2(acc[i][1], a, w1);
            }
        }
        __syncthreads();
    }
    float2 b0 = *(const float2*)&b[2 * tx];
    float2 b1 = *(const float2*)&b[2 * tx + 64];
#pragma unroll
    for (int i = 0; i < 16; i++) {
        int n = row0 + ty * 16 + i;
        if (n < NN) {
            float2 v0 = unpack2(acc[i][0]);
            float2 v1 = unpack2(acc[i][1]);
            v0.x += b0.x; v0.y += b0.y;
            v1.x += b1.x; v1.y += b1.y;
            if (use_res) {
                float2 r0 = *(const float2*)&g_h[n * HID + 2 * tx];
                float2 r1 = *(const float2*)&g_h[n * HID + 2 * tx + 64];
                v0.x += r0.x; v0.y += r0.y;
                v1.x += r1.x; v1.y += r1.y;
            }
            *(float2*)&g_h[n * HID + 2 * tx] = v0;
            *(float2*)&g_h[n * HID + 2 * tx + 64] = v1;
        }
    }
}

// ---------------- classifier ----------------
__global__ __launch_bounds__(256) void k_classifier(
    const float* __restrict__ gmm, const float* __restrict__ bb,
    const float* __restrict__ lw, const float* __restrict__ lbias,
    float* __restrict__ out)
{
    int lane = threadIdx.x & 31;
    int n = (blockIdx.x * 256 + threadIdx.x) >> 5;
    if (n >= NN) return;
    float4 v = ((const float4*)g_h)[n * 32 + lane];
    float s = v.x + v.y + v.z + v.w;
    float q = v.x * v.x + v.y * v.y + v.z * v.z + v.w * v.w;
#pragma unroll
    for (int off = 16; off; off >>= 1) {
        s += __shfl_xor_sync(0xffffffffu, s, off);
        q += __shfl_xor_sync(0xffffffffu, q, off);
    }
    float m = s * (1.f / 128.f);
    float var = q * (1.f / 128.f) - m * m;
    float rstd = rsqrtf(var + 1e-5f);
    float4 g4 = ((const float4*)gmm)[lane];
    float4 b4 = ((const float4*)bb)[lane];
    float h0 = fmaxf((v.x - m) * rstd * g4.x + b4.x, 0.f);
    float h1 = fmaxf((v.y - m) * rstd * g4.y + b4.y, 0.f);
    float h2 = fmaxf((v.z - m) * rstd * g4.z + b4.z, 0.f);
    float h3 = fmaxf((v.w - m) * rstd * g4.w + b4.w, 0.f);
    int c0 = lane * 4;
    float r[NCLS];
#pragma unroll
    for (int j = 0; j < NCLS; j++) {
        float p = h0 * lw[c0 * NCLS + j];
        p = fmaf(h1, lw[(c0 + 1) * NCLS + j], p);
        p = fmaf(h2, lw[(c0 + 2) * NCLS + j], p);
        p = fmaf(h3, lw[(c0 + 3) * NCLS + j], p);
#pragma unroll
        for (int off = 16; off; off >>= 1) p += __shfl_xor_sync(0xffffffffu, p, off);
        r[j] = p;
    }
#pragma unroll
    for (int j = 0; j < NCLS; j++)
        if (lane == j) out[n * NCLS + j] = r[j] + lbias[j];
}

// ---------------- launch ----------------
extern "C" void kernel_launch(void* const* d_in, const int* in_sizes, int n_in,
                              void* d_out, int out_size)
{
    const float* x         = (const float*)d_in[0];
    const float* edge_attr = (const float*)d_in[1];
    const float* node_w    = (const float*)d_in[2];
    const float* node_b    = (const float*)d_in[3];
    const float* edge_w    = (const float*)d_in[4];
    const float* edge_b    = (const float*)d_in[5];
    const float* mlp1_w    = (const float*)d_in[6];
    const float* mlp1_b    = (const float*)d_in[7];
    const float* ln_g      = (const float*)d_in[8];
    const float* ln_b      = (const float*)d_in[9];
    const float* mlp2_w    = (const float*)d_in[10];
    const float* mlp2_b    = (const float*)d_in[11];
    const float* t         = (const float*)d_in[12];
    const float* norm_g    = (const float*)d_in[13];
    const float* norm_b    = (const float*)d_in[14];
    const float* lin_w     = (const float*)d_in[15];
    const float* lin_b     = (const float*)d_in[16];
    const int*   edge_index= (const int*)d_in[17];
    const int* src = edge_index;
    const int* dst = edge_index + NE;
    float* out = (float*)d_out;

    k_zero_cnt<<<(NN + 255) / 256, 256>>>();
    k_hist<<<(NE + 255) / 256, 256>>>(dst);
    k_scan<<<1, 1024>>>();
    k_scatter<<<(NE + 255) / 256, 256>>>(dst);

    k_edge_enc<<<NE / 128, 256>>>(edge_attr, src, edge_w, edge_b);
    k_node_enc<<<1184, 256>>>(x, node_w, node_b);

    for (int l = 0; l < 3; l++) {
        if (l > 0)
            k_prenorm<<<(NN * 32 + 255) / 256, 256>>>(norm_g + l * HID, norm_b + l * HID);
        k_edge_agg<<<(NN * 32 + 255) / 256, 256>>>(l, t);
        k_gemm1<<<(NN + 63) / 64, 256>>>(l, mlp1_w + l * HID * 2 * HID, mlp1_b + l * 2 * HID,
                                         ln_g + l * 2 * HID, ln_b + l * 2 * HID);
        k_gemm2<<<(NN + 127) / 128, 256>>>(mlp2_w + l * 2 * HID * HID, mlp2_b + l * HID, l > 0);
    }
    k_classifier<<<(NN * 32 + 255) / 256, 256>>>(norm_g, norm_b, lin_w, lin_b, out);
}

// round 4
// speedup vs baseline: 1.1526x; 1.0842x over previous
#include <cuda_runtime.h>
#include <cuda_fp16.h>

#define NN 30000
#define NE 480000
#define HID 128
#define F_IN 64
#define F_EDGE 16
#define NCLS 10

typedef unsigned long long ull;

__device__ __forceinline__ ull pack2(float lo, float hi) {
    ull r; asm("mov.b64 %0, {%1, %2};" : "=l"(r) : "f"(lo), "f"(hi)); return r;
}
__device__ __forceinline__ float2 unpack2(ull v) {
    float2 r; asm("mov.b64 {%0, %1}, %2;" : "=f"(r.x), "=f"(r.y) : "l"(v)); return r;
}
__device__ __forceinline__ void fma2(ull& d, ull a, ull b) {
    asm("fma.rn.f32x2 %0, %1, %2, %0;" : "+l"(d) : "l"(a), "l"(b));
}

// ---------------- device scratch ----------------
__device__ __align__(16) __half g_eah[(size_t)NE * HID];  // dst-sorted edge encodings, fp16
__device__ int   g_srcs[NE];
__device__ int   g_rowptr[NN + 1];
__device__ int   g_cnt[NN];                               // zero at module load; re-zeroed each replay (last kernel)
__device__ __align__(16) float  g_h[NN * HID];            // running node features (fp32)
__device__ __align__(16) float  g_nin[NN * HID];          // conv input fp32 (prenormed), layers 1,2
__device__ __align__(16) __half g_ninh[NN * HID];         // fp16 gather table (h0 for l=0, nin for l>0)
__device__ __align__(16) float  g_z[NN * HID];            // agg + x  (gemm1 input)
__device__ __align__(16) float  g_mid[NN * 2 * HID];

// ---------------- CSR build ----------------
__global__ void k_zero_cnt() {
    int i = blockIdx.x * blockDim.x + threadIdx.x;
    if (i < NN) g_cnt[i] = 0;
}

__global__ void k_hist(const int* __restrict__ dst) {
    int i = blockIdx.x * blockDim.x + threadIdx.x;
    if (i < NE) atomicAdd(&g_cnt[dst[i]], 1);
}

// exclusive scan of g_cnt into g_rowptr; zeroes g_cnt (for rank atomics in encoder)
__global__ __launch_bounds__(1024) void k_scan() {
    __shared__ int wsum[32];
    const int CH = 30;
    int tid = threadIdx.x;
    int base = tid * CH;
    int loc[CH];
    int s = 0;
#pragma unroll
    for (int i = 0; i < CH; i++) {
        int idx = base + i;
        loc[i] = (idx < NN) ? g_cnt[idx] : 0;
        s += loc[i];
    }
    int lane = tid & 31, wid = tid >> 5;
    int v = s;
#pragma unroll
    for (int off = 1; off < 32; off <<= 1) {
        int t = __shfl_up_sync(0xffffffffu, v, off);
        if (lane >= off) v += t;
    }
    if (lane == 31) wsum[wid] = v;
    __syncthreads();
    if (wid == 0) {
        int wv = wsum[lane];
#pragma unroll
        for (int off = 1; off < 32; off <<= 1) {
            int t = __shfl_up_sync(0xffffffffu, wv, off);
            if (lane >= off) wv += t;
        }
        wsum[lane] = wv;
    }
    __syncthreads();
    int run = v - s + (wid ? wsum[wid - 1] : 0);
#pragma unroll
    for (int i = 0; i < CH; i++) {
        int idx = base + i;
        if (idx < NN) {
            g_rowptr[idx] = run;
            run += loc[i];
            g_cnt[idx] = 0;
        }
    }
    if (tid == 1023) g_rowptr[NN] = run;
}

// ---------------- fused edge encoder + scatter ----------------
// Block handles 128 original edges; computes ea = attr@W+b (fp16), places each
// row at its dst-sorted position via atomic rank. Coalesced attr reads.
__global__ __launch_bounds__(256) void k_encscatter(
    const float* __restrict__ edge_attr, const int* __restrict__ src,
    const int* __restrict__ dst,
    const float* __restrict__ W, const float* __restrict__ bias)
{
    __shared__ ull sA2[128][17];
    __shared__ __align__(16) float sW[F_EDGE][HID];
    __shared__ int sPos[128];
    int p0 = blockIdx.x * 128;
    int tid = threadIdx.x;
    for (int i = tid; i < F_EDGE * HID; i += 256) ((float*)sW)[i] = W[i];
    if (tid < 128) {
        int e = p0 + tid;
        int d = dst[e];
        int rank = atomicAdd(&g_cnt[d], 1);
        int pos = g_rowptr[d] + rank;
        sPos[tid] = pos;
        g_srcs[pos] = src[e];
    }
    __syncthreads();
#pragma unroll
    for (int i = 0; i < 8; i++) {
        int idx = tid + i * 256;
        int r = idx >> 4, k = idx & 15;
        float v = edge_attr[(size_t)(p0 + r) * F_EDGE + k];   // coalesced
        sA2[r][k] = pack2(v, v);
    }
    __syncthreads();
    int tx = tid & 31, ty = tid >> 5;
    float2 b0 = *(const float2*)&bias[2 * tx];
    float2 b1 = *(const float2*)&bias[2 * tx + 64];
    ull ib0 = pack2(b0.x, b0.y), ib1 = pack2(b1.x, b1.y);
    ull acc[16][2];
#pragma unroll
    for (int i = 0; i < 16; i++) { acc[i][0] = ib0; acc[i][1] = ib1; }
#pragma unroll
    for (int k = 0; k < F_EDGE; k++) {
        ull w0 = *(const ull*)&sW[k][2 * tx];
        ull w1 = *(const ull*)&sW[k][2 * tx + 64];
#pragma unroll
        for (int i = 0; i < 16; i++) {
            ull a = sA2[ty * 16 + i][k];
            fma2(acc[i][0], a, w0);
            fma2(acc[i][1], a, w1);
        }
    }
#pragma unroll
    for (int i = 0; i < 16; i++) {
        size_t p = sPos[ty * 16 + i];
        float2 v0 = unpack2(acc[i][0]);
        float2 v1 = unpack2(acc[i][1]);
        *(__half2*)&g_eah[p * HID + 2 * tx]      = __float22half2_rn(v0);
        *(__half2*)&g_eah[p * HID + 2 * tx + 64] = __float22half2_rn(v1);
    }
}

// ---------------- node encoder: writes g_h (fp32) + g_ninh (fp16) ----------------
__global__ __launch_bounds__(256) void k_node_enc(
    const float* __restrict__ x, const float* __restrict__ W, const float* __restrict__ bias)
{
    __shared__ __align__(16) float sW[F_IN * HID];
    __shared__ __align__(16) float sB[HID];
    for (int i = threadIdx.x; i < F_IN * HID; i += 256) sW[i] = W[i];
    if (threadIdx.x < HID) sB[threadIdx.x] = bias[threadIdx.x];
    __syncthreads();
    int lane = threadIdx.x & 31;
    int warp = (blockIdx.x * 256 + threadIdx.x) >> 5;
    int nw = gridDim.x * 8;
    float4 bv = ((float4*)sB)[lane];
    for (int n = warp; n < NN; n += nw) {
        float a0 = x[n * F_IN + lane];
        float a1 = x[n * F_IN + 32 + lane];
        float4 acc = bv;
#pragma unroll
        for (int k = 0; k < F_IN; k++) {
            float ak = __shfl_sync(0xffffffffu, (k < 32) ? a0 : a1, k & 31);
            float4 w = ((const float4*)(sW + k * HID))[lane];
            acc.x = fmaf(ak, w.x, acc.x);
            acc.y = fmaf(ak, w.y, acc.y);
            acc.z = fmaf(ak, w.z, acc.z);
            acc.w = fmaf(ak, w.w, acc.w);
        }
        ((float4*)g_h)[n * 32 + lane] = acc;
        __half2 h0 = __float22half2_rn(make_float2(acc.x, acc.y));
        __half2 h1 = __float22half2_rn(make_float2(acc.z, acc.w));
        *(__half2*)&g_ninh[(size_t)n * HID + 4 * lane]     = h0;
        *(__half2*)&g_ninh[(size_t)n * HID + 4 * lane + 2] = h1;
    }
}

// ---------------- edge aggregation: fp16 tables, z = agg + x ----------------
__device__ __forceinline__ float4 load_h16(const __half* base, size_t row, int lane) {
    uint2 raw = *(const uint2*)(base + row * HID + lane * 4);
    float2 fa = __half22float2(*(__half2*)&raw.x);
    float2 fb = __half22float2(*(__half2*)&raw.y);
    return make_float4(fa.x, fa.y, fb.x, fb.y);
}

__global__ __launch_bounds__(256) void k_edge_agg(int layer, const float* __restrict__ t_arr)
{
    int lane = threadIdx.x & 31;
    int n = (blockIdx.x * 256 + threadIdx.x) >> 5;
    if (n >= NN) return;
    const float4* x4 = (const float4*)((layer == 0) ? g_h : g_nin);
    float tv = t_arr[layer];
    int p = g_rowptr[n], end = g_rowptr[n + 1];
    float4 sa = make_float4(0.f, 0.f, 0.f, 0.f), wa = sa;
    float4 sb = sa, wb = sa;
    for (; p + 4 <= end; p += 4) {
        int s0 = g_srcs[p], s1 = g_srcs[p + 1], s2 = g_srcs[p + 2], s3 = g_srcs[p + 3];
        float4 e0 = load_h16(g_eah, p, lane);
        float4 e1 = load_h16(g_eah, p + 1, lane);
        float4 e2 = load_h16(g_eah, p + 2, lane);
        float4 e3 = load_h16(g_eah, p + 3, lane);
        float4 h0 = load_h16(g_ninh, s0, lane);
        float4 h1 = load_h16(g_ninh, s1, lane);
        float4 h2 = load_h16(g_ninh, s2, lane);
        float4 h3 = load_h16(g_ninh, s3, lane);
#define DO_EDGE(hh, ee, S, W) { \
        float m0 = fmaxf(hh.x + ee.x, 0.f) + 1e-7f; \
        float m1 = fmaxf(hh.y + ee.y, 0.f) + 1e-7f; \
        float m2 = fmaxf(hh.z + ee.z, 0.f) + 1e-7f; \
        float m3 = fmaxf(hh.w + ee.w, 0.f) + 1e-7f; \
        float x0 = __expf(m0 * tv), x1 = __expf(m1 * tv); \
        float x2 = __expf(m2 * tv), x3 = __expf(m3 * tv); \
        S.x += x0; S.y += x1; S.z += x2; S.w += x3; \
        W.x = fmaf(m0, x0, W.x); W.y = fmaf(m1, x1, W.y); \
        W.z = fmaf(m2, x2, W.z); W.w = fmaf(m3, x3, W.w); }
        DO_EDGE(h0, e0, sa, wa);
        DO_EDGE(h1, e1, sb, wb);
        DO_EDGE(h2, e2, sa, wa);
        DO_EDGE(h3, e3, sb, wb);
    }
    for (; p < end; p++) {
        int s0 = g_srcs[p];
        float4 e0 = load_h16(g_eah, p, lane);
        float4 h0 = load_h16(g_ninh, s0, lane);
        DO_EDGE(h0, e0, sa, wa);
    }
#undef DO_EDGE
    sa.x += sb.x; sa.y += sb.y; sa.z += sb.z; sa.w += sb.w;
    wa.x += wb.x; wa.y += wb.y; wa.z += wb.z; wa.w += wb.w;
    float4 xr = x4[n * 32 + lane];
    float4 o;
    o.x = wa.x / (sa.x + 1e-16f) + xr.x;
    o.y = wa.y / (sa.y + 1e-16f) + xr.y;
    o.z = wa.z / (sa.z + 1e-16f) + xr.z;
    o.w = wa.w / (sa.w + 1e-16f) + xr.w;
    ((float4*)g_z)[n * 32 + lane] = o;
}

// ---------------- GEMM1: mid = relu(LN(z @ W1 + b1)), 64x256 tile, f32x2 ----------------
__global__ __launch_bounds__(256) void k_gemm1(
    const float* __restrict__ W, const float* __restrict__ b,
    const float* __restrict__ lg, const float* __restrict__ lb)
{
    __shared__ ull sA2[64][33];
    __shared__ __align__(16) float sW[32][256];
    int tx = threadIdx.x & 31, ty = threadIdx.x >> 5;
    int row0 = blockIdx.x * 64;
    ull acc[8][4];
#pragma unroll
    for (int i = 0; i < 8; i++)
#pragma unroll
        for (int jp = 0; jp < 4; jp++) acc[i][jp] = 0ull;

    for (int kc = 0; kc < HID; kc += 32) {
#pragma unroll
        for (int i = 0; i < 8; i++) {
            int idx = threadIdx.x + i * 256;
            int r = idx >> 5, k = idx & 31;
            int n = row0 + r;
            float v = (n < NN) ? g_z[n * HID + kc + k] : 0.f;
            sA2[r][k] = pack2(v, v);
        }
#pragma unroll
        for (int i = 0; i < 8; i++) {
            int idx = threadIdx.x + i * 256;
            int kk = idx >> 6, c4 = idx & 63;
            ((float4*)sW[kk])[c4] = ((const float4*)(W + (kc + kk) * 256))[c4];
        }
        __syncthreads();
#pragma unroll 8
        for (int k = 0; k < 32; k++) {
            ull a[8];
#pragma unroll
            for (int i = 0; i < 8; i++) a[i] = sA2[ty * 8 + i][k];
            ull w[4];
#pragma unroll
            for (int jp = 0; jp < 4; jp++) w[jp] = *(const ull*)&sW[k][2 * tx + 64 * jp];
#pragma unroll
            for (int i = 0; i < 8; i++)
#pragma unroll
                for (int jp = 0; jp < 4; jp++) fma2(acc[i][jp], a[i], w[jp]);
        }
        __syncthreads();
    }
    float2 bias[4], gg[4], bb2[4];
#pragma unroll
    for (int jp = 0; jp < 4; jp++) {
        int c = 2 * tx + 64 * jp;
        bias[jp] = *(const float2*)&b[c];
        gg[jp]   = *(const float2*)&lg[c];
        bb2[jp]  = *(const float2*)&lb[c];
    }
#pragma unroll
    for (int i = 0; i < 8; i++) {
        float2 v[4];
        float sum = 0.f, sq = 0.f;
#pragma unroll
        for (int jp = 0; jp < 4; jp++) {
            v[jp] = unpack2(acc[i][jp]);
            v[jp].x += bias[jp].x; v[jp].y += bias[jp].y;
            sum += v[jp].x + v[jp].y;
            sq = fmaf(v[jp].x, v[jp].x, sq);
            sq = fmaf(v[jp].y, v[jp].y, sq);
        }
#pragma unroll
        for (int off = 16; off; off >>= 1) {
            sum += __shfl_xor_sync(0xffffffffu, sum, off);
            sq += __shfl_xor_sync(0xffffffffu, sq, off);
        }
        float m = sum * (1.f / 256.f);
        float var = sq * (1.f / 256.f) - m * m;
        float rstd = rsqrtf(var + 1e-5f);
        int n = row0 + ty * 8 + i;
        if (n < NN) {
#pragma unroll
            for (int jp = 0; jp < 4; jp++) {
                float2 o;
                o.x = fmaxf((v[jp].x - m) * rstd * gg[jp].x + bb2[jp].x, 0.f);
                o.y = fmaxf((v[jp].y - m) * rstd * gg[jp].y + bb2[jp].y, 0.f);
                *(float2*)&g_mid[n * 256 + 2 * tx + 64 * jp] = o;
            }
        }
    }
}

// ---------------- GEMM2: h = mid @ W2 + b2 (+res); optional fused prenorm for next layer ----------------
__global__ __launch_bounds__(256) void k_gemm2(
    const float* __restrict__ W, const float* __restrict__ b, int use_res,
    const float* __restrict__ gn, const float* __restrict__ bn, int write_pre)
{
    __shared__ ull sA2[128][33];
    __shared__ __align__(16) float sW[32][128];
    int tx = threadIdx.x & 31, ty = threadIdx.x >> 5;
    int row0 = blockIdx.x * 128;
    ull acc[16][2];
#pragma unroll
    for (int i = 0; i < 16; i++) { acc[i][0] = 0ull; acc[i][1] = 0ull; }

    for (int kc = 0; kc < 256; kc += 32) {
#pragma unroll
        for (int i = 0; i < 16; i++) {
            int idx = threadIdx.x + i * 256;
            int r = idx >> 5, k = idx & 31;
            int n = row0 + r;
            float v = (n < NN) ? g_mid[n * 256 + kc + k] : 0.f;
            sA2[r][k] = pack2(v, v);
        }
#pragma unroll
        for (int i = 0; i < 4; i++) {
            int idx = threadIdx.x + i * 256;
            int kk = idx >> 5, c4 = idx & 31;
            ((float4*)sW[kk])[c4] = ((const float4*)(W + (kc + kk) * 128))[c4];
        }
        __syncthreads();
#pragma unroll 4
        for (int k = 0; k < 32; k++) {
            ull w0 = *(const ull*)&sW[k][2 * tx];
            ull w1 = *(const ull*)&sW[k][2 * tx + 64];
#pragma unroll
            for (int i = 0; i < 16; i++) {
                ull a = sA2[ty * 16 + i][k];
                fma2(acc[i][0], a, w0);
                fma2(acc[i][1], a, w1);
            }
        }
        __syncthreads();
    }
    float2 b0 = *(const float2*)&b[2 * tx];
    float2 b1 = *(const float2*)&b[2 * tx + 64];
    float2 gn0, gn1, bn0, bn1;
    if (write_pre) {
        gn0 = *(const float2*)&gn[2 * tx];
        gn1 = *(const float2*)&gn[2 * tx + 64];
        bn0 = *(const float2*)&bn[2 * tx];
        bn1 = *(const float2*)&bn[2 * tx + 64];
    }
#pragma unroll
    for (int i = 0; i < 16; i++) {
        int n = row0 + ty * 16 + i;
        if (n >= NN) continue;
        float2 v0 = unpack2(acc[i][0]);
        float2 v1 = unpack2(acc[i][1]);
        v0.x += b0.x; v0.y += b0.y;
        v1.x += b1.x; v1.y += b1.y;
        if (use_res) {
            float2 r0 = *(const float2*)&g_h[n * HID + 2 * tx];
            float2 r1 = *(const float2*)&g_h[n * HID + 2 * tx + 64];
            v0.x += r0.x; v0.y += r0.y;
            v1.x += r1.x; v1.y += r1.y;
        }
        *(float2*)&g_h[n * HID + 2 * tx] = v0;
        *(float2*)&g_h[n * HID + 2 * tx + 64] = v1;
        if (write_pre) {
            // fused prenorm for the NEXT layer: nin = relu(LN(h))
            float sum = v0.x + v0.y + v1.x + v1.y;
            float sq = v0.x * v0.x + v0.y * v0.y + v1.x * v1.x + v1.y * v1.y;
#pragma unroll
            for (int off = 16; off; off >>= 1) {
                sum += __shfl_xor_sync(0xffffffffu, sum, off);
                sq += __shfl_xor_sync(0xffffffffu, sq, off);
            }
            float m = sum * (1.f / 128.f);
            float var = sq * (1.f / 128.f) - m * m;
            float rstd = rsqrtf(var + 1e-5f);
            float2 o0, o1;
            o0.x = fmaxf((v0.x - m) * rstd * gn0.x + bn0.x, 0.f);
            o0.y = fmaxf((v0.y - m) * rstd * gn0.y + bn0.y, 0.f);
            o1.x = fmaxf((v1.x - m) * rstd * gn1.x + bn1.x, 0.f);
            o1.y = fmaxf((v1.y - m) * rstd * gn1.y + bn1.y, 0.f);
            *(float2*)&g_nin[n * HID + 2 * tx] = o0;
            *(float2*)&g_nin[n * HID + 2 * tx + 64] = o1;
            *(__half2*)&g_ninh[(size_t)n * HID + 2 * tx]      = __float22half2_rn(o0);
            *(__half2*)&g_ninh[(size_t)n * HID + 2 * tx + 64] = __float22half2_rn(o1);
        }
    }
}

// ---------------- classifier: out = relu(LN(h, g0, b0)) @ lin_w + lin_b ----------------
__global__ __launch_bounds__(256) void k_classifier(
    const float* __restrict__ gmm, const float* __restrict__ bb,
    const float* __restrict__ lw, const float* __restrict__ lbias,
    float* __restrict__ out)
{
    int lane = threadIdx.x & 31;
    int n = (blockIdx.x * 256 + threadIdx.x) >> 5;
    if (n >= NN) return;
    float4 v = ((const float4*)g_h)[n * 32 + lane];
    float s = v.x + v.y + v.z + v.w;
    float q = v.x * v.x + v.y * v.y + v.z * v.z + v.w * v.w;
#pragma unroll
    for (int off = 16; off; off >>= 1) {
        s += __shfl_xor_sync(0xffffffffu, s, off);
        q += __shfl_xor_sync(0xffffffffu, q, off);
    }
    float m = s * (1.f / 128.f);
    float var = q * (1.f / 128.f) - m * m;
    float rstd = rsqrtf(var + 1e-5f);
    float4 g4 = ((const float4*)gmm)[lane];
    float4 b4 = ((const float4*)bb)[lane];
    float h0 = fmaxf((v.x - m) * rstd * g4.x + b4.x, 0.f);
    float h1 = fmaxf((v.y - m) * rstd * g4.y + b4.y, 0.f);
    float h2 = fmaxf((v.z - m) * rstd * g4.z + b4.z, 0.f);
    float h3 = fmaxf((v.w - m) * rstd * g4.w + b4.w, 0.f);
    int c0 = lane * 4;
    float r[NCLS];
#pragma unroll
    for (int j = 0; j < NCLS; j++) {
        float p = h0 * lw[c0 * NCLS + j];
        p = fmaf(h1, lw[(c0 + 1) * NCLS + j], p);
        p = fmaf(h2, lw[(c0 + 2) * NCLS + j], p);
        p = fmaf(h3, lw[(c0 + 3) * NCLS + j], p);
#pragma unroll
        for (int off = 16; off; off >>= 1) p += __shfl_xor_sync(0xffffffffu, p, off);
        r[j] = p;
    }
#pragma unroll
    for (int j = 0; j < NCLS; j++)
        if (lane == j) out[n * NCLS + j] = r[j] + lbias[j];
}

// ---------------- launch ----------------
extern "C" void kernel_launch(void* const* d_in, const int* in_sizes, int n_in,
                              void* d_out, int out_size)
{
    const float* x         = (const float*)d_in[0];
    const float* edge_attr = (const float*)d_in[1];
    const float* node_w    = (const float*)d_in[2];
    const float* node_b    = (const float*)d_in[3];
    const float* edge_w    = (const float*)d_in[4];
    const float* edge_b    = (const float*)d_in[5];
    const float* mlp1_w    = (const float*)d_in[6];
    const float* mlp1_b    = (const float*)d_in[7];
    const float* ln_g      = (const float*)d_in[8];
    const float* ln_b      = (const float*)d_in[9];
    const float* mlp2_w    = (const float*)d_in[10];
    const float* mlp2_b    = (const float*)d_in[11];
    const float* t         = (const float*)d_in[12];
    const float* norm_g    = (const float*)d_in[13];
    const float* norm_b    = (const float*)d_in[14];
    const float* lin_w     = (const float*)d_in[15];
    const float* lin_b     = (const float*)d_in[16];
    const int*   edge_index= (const int*)d_in[17];
    const int* src = edge_index;
    const int* dst = edge_index + NE;
    float* out = (float*)d_out;

    // g_cnt is zero on entry (module-load zero on first call; trailing k_zero_cnt on replays)
    k_node_enc<<<1184, 256>>>(x, node_w, node_b);                 // 0
    k_hist<<<(NE + 255) / 256, 256>>>(dst);                       // 1
    k_scan<<<1, 1024>>>();                                        // 2 (zeroes g_cnt for ranks)
    k_encscatter<<<NE / 128, 256>>>(edge_attr, src, dst, edge_w, edge_b);  // 3 <- profiled

    for (int l = 0; l < 3; l++) {
        k_edge_agg<<<(NN * 32 + 255) / 256, 256>>>(l, t);
        k_gemm1<<<(NN + 63) / 64, 256>>>(mlp1_w + l * HID * 2 * HID, mlp1_b + l * 2 * HID,
                                         ln_g + l * 2 * HID, ln_b + l * 2 * HID);
        int wp = (l < 2) ? 1 : 0;
        k_gemm2<<<(NN + 127) / 128, 256>>>(mlp2_w + l * 2 * HID * HID, mlp2_b + l * HID,
                                           l > 0,
                                           norm_g + (l + 1) * HID, norm_b + (l + 1) * HID, wp);
    }
    k_classifier<<<(NN * 32 + 255) / 256, 256>>>(norm_g, norm_b, lin_w, lin_b, out);
    k_zero_cnt<<<(NN + 255) / 256, 256>>>();   // leave g_cnt clean for next replay
}

// round 8
// speedup vs baseline: 1.2220x; 1.0602x over previous
#include <cuda_runtime.h>
#include <cuda_fp16.h>
#include <cuda_bf16.h>
#include <mma.h>
#include <cstdint>

using namespace nvcuda;

#define NN 30000
#define NE 480000
#define HID 128
#define F_IN 64
#define F_EDGE 16
#define NCLS 10

typedef unsigned long long ull;

__device__ __forceinline__ ull pack2(float lo, float hi) {
    ull r; asm("mov.b64 %0, {%1, %2};" : "=l"(r) : "f"(lo), "f"(hi)); return r;
}
__device__ __forceinline__ float2 unpack2(ull v) {
    float2 r; asm("mov.b64 {%0, %1}, %2;" : "=f"(r.x), "=f"(r.y) : "l"(v)); return r;
}
__device__ __forceinline__ void fma2(ull& d, ull a, ull b) {
    asm("fma.rn.f32x2 %0, %1, %2, %0;" : "+l"(d) : "l"(a), "l"(b));
}

// ---------------- device scratch ----------------
__device__ __align__(16) __half g_eah[(size_t)NE * HID];
__device__ int   g_srcs[NE];
__device__ int   g_rowptr[NN + 1];
__device__ int   g_cnt[NN];
__device__ __align__(16) float  g_h[NN * HID];
__device__ __align__(16) float  g_nin[NN * HID];
__device__ __align__(16) __half g_ninh[NN * HID];
__device__ __align__(16) __nv_bfloat16 g_zh[NN * HID];
__device__ __align__(16) __nv_bfloat16 g_zl[NN * HID];
__device__ __align__(16) __nv_bfloat16 g_midh[(size_t)NN * 256];
__device__ __align__(16) __nv_bfloat16 g_midl[(size_t)NN * 256];
__device__ __align__(16) __nv_bfloat16 g_w1h[3 * 256 * 128];   // W1^T hi: (n,k) at n*128+k
__device__ __align__(16) __nv_bfloat16 g_w1l[3 * 256 * 128];
__device__ __align__(16) __nv_bfloat16 g_w2h[3 * 128 * 256];   // W2^T hi: (n,k) at n*256+k
__device__ __align__(16) __nv_bfloat16 g_w2l[3 * 128 * 256];

// ---------------- CSR build ----------------
__global__ void k_zero_cnt() {
    int i = blockIdx.x * blockDim.x + threadIdx.x;
    if (i < NN) g_cnt[i] = 0;
}

__global__ void k_hist(const int* __restrict__ dst) {
    int i = blockIdx.x * blockDim.x + threadIdx.x;
    if (i < NE) atomicAdd(&g_cnt[dst[i]], 1);
}

__global__ __launch_bounds__(1024) void k_scan() {
    __shared__ int wsum[32];
    const int CH = 30;
    int tid = threadIdx.x;
    int base = tid * CH;
    int loc[CH];
    int s = 0;
#pragma unroll
    for (int i = 0; i < CH; i++) {
        int idx = base + i;
        loc[i] = (idx < NN) ? g_cnt[idx] : 0;
        s += loc[i];
    }
    int lane = tid & 31, wid = tid >> 5;
    int v = s;
#pragma unroll
    for (int off = 1; off < 32; off <<= 1) {
        int t = __shfl_up_sync(0xffffffffu, v, off);
        if (lane >= off) v += t;
    }
    if (lane == 31) wsum[wid] = v;
    __syncthreads();
    if (wid == 0) {
        int wv = wsum[lane];
#pragma unroll
        for (int off = 1; off < 32; off <<= 1) {
            int t = __shfl_up_sync(0xffffffffu, wv, off);
            if (lane >= off) wv += t;
        }
        wsum[lane] = wv;
    }
    __syncthreads();
    int run = v - s + (wid ? wsum[wid - 1] : 0);
#pragma unroll
    for (int i = 0; i < CH; i++) {
        int idx = base + i;
        if (idx < NN) {
            g_rowptr[idx] = run;
            run += loc[i];
            g_cnt[idx] = 0;
        }
    }
    if (tid == 1023) g_rowptr[NN] = run;
}

// ---------------- fused edge encoder + scatter ----------------
__global__ __launch_bounds__(256) void k_encscatter(
    const float* __restrict__ edge_attr, const int* __restrict__ src,
    const int* __restrict__ dst,
    const float* __restrict__ W, const float* __restrict__ bias)
{
    __shared__ ull sA2[128][17];
    __shared__ __align__(16) float sW[F_EDGE][HID];
    __shared__ int sPos[128];
    int p0 = blockIdx.x * 128;
    int tid = threadIdx.x;
    for (int i = tid; i < F_EDGE * HID; i += 256) ((float*)sW)[i] = W[i];
    if (tid < 128) {
        int e = p0 + tid;
        int d = dst[e];
        int rank = atomicAdd(&g_cnt[d], 1);
        int pos = g_rowptr[d] + rank;
        sPos[tid] = pos;
        g_srcs[pos] = src[e];
    }
    __syncthreads();
#pragma unroll
    for (int i = 0; i < 8; i++) {
        int idx = tid + i * 256;
        int r = idx >> 4, k = idx & 15;
        float v = edge_attr[(size_t)(p0 + r) * F_EDGE + k];
        sA2[r][k] = pack2(v, v);
    }
    __syncthreads();
    int tx = tid & 31, ty = tid >> 5;
    float2 b0 = *(const float2*)&bias[2 * tx];
    float2 b1 = *(const float2*)&bias[2 * tx + 64];
    ull ib0 = pack2(b0.x, b0.y), ib1 = pack2(b1.x, b1.y);
    ull acc[16][2];
#pragma unroll
    for (int i = 0; i < 16; i++) { acc[i][0] = ib0; acc[i][1] = ib1; }
#pragma unroll
    for (int k = 0; k < F_EDGE; k++) {
        ull w0 = *(const ull*)&sW[k][2 * tx];
        ull w1 = *(const ull*)&sW[k][2 * tx + 64];
#pragma unroll
        for (int i = 0; i < 16; i++) {
            ull a = sA2[ty * 16 + i][k];
            fma2(acc[i][0], a, w0);
            fma2(acc[i][1], a, w1);
        }
    }
#pragma unroll
    for (int i = 0; i < 16; i++) {
        size_t p = sPos[ty * 16 + i];
        float2 v0 = unpack2(acc[i][0]);
        float2 v1 = unpack2(acc[i][1]);
        *(__half2*)&g_eah[p * HID + 2 * tx]      = __float22half2_rn(v0);
        *(__half2*)&g_eah[p * HID + 2 * tx + 64] = __float22half2_rn(v1);
    }
}

// ---------------- weight conversion: W1^T, W2^T -> bf16 hi/lo planes ----------------
__global__ __launch_bounds__(256) void k_wconv(const float* __restrict__ w1,
                                               const float* __restrict__ w2)
{
    int i = blockIdx.x * 256 + threadIdx.x;
    if (i < 3 * 256 * 128) {
        int l = i >> 15, rem = i & 32767;
        int n = rem >> 7, k = rem & 127;
        float v = w1[l * 32768 + k * 256 + n];
        __nv_bfloat16 hi = __float2bfloat16(v);
        g_w1h[i] = hi;
        g_w1l[i] = __float2bfloat16(v - __bfloat162float(hi));

        int n2 = rem >> 8, k2 = rem & 255;
        float v2 = w2[l * 32768 + k2 * 128 + n2];
        __nv_bfloat16 hi2 = __float2bfloat16(v2);
        g_w2h[i] = hi2;
        g_w2l[i] = __float2bfloat16(v2 - __bfloat162float(hi2));
    }
}

// ---------------- node encoder ----------------
__global__ __launch_bounds__(256) void k_node_enc(
    const float* __restrict__ x, const float* __restrict__ W, const float* __restrict__ bias)
{
    __shared__ __align__(16) float sW[F_IN * HID];
    __shared__ __align__(16) float sB[HID];
    for (int i = threadIdx.x; i < F_IN * HID; i += 256) sW[i] = W[i];
    if (threadIdx.x < HID) sB[threadIdx.x] = bias[threadIdx.x];
    __syncthreads();
    int lane = threadIdx.x & 31;
    int warp = (blockIdx.x * 256 + threadIdx.x) >> 5;
    int nw = gridDim.x * 8;
    float4 bv = ((float4*)sB)[lane];
    for (int n = warp; n < NN; n += nw) {
        float a0 = x[n * F_IN + lane];
        float a1 = x[n * F_IN + 32 + lane];
        float4 acc = bv;
#pragma unroll
        for (int k = 0; k < F_IN; k++) {
            float ak = __shfl_sync(0xffffffffu, (k < 32) ? a0 : a1, k & 31);
            float4 w = ((const float4*)(sW + k * HID))[lane];
            acc.x = fmaf(ak, w.x, acc.x);
            acc.y = fmaf(ak, w.y, acc.y);
            acc.z = fmaf(ak, w.z, acc.z);
            acc.w = fmaf(ak, w.w, acc.w);
        }
        ((float4*)g_h)[n * 32 + lane] = acc;
        __half2 h0 = __float22half2_rn(make_float2(acc.x, acc.y));
        __half2 h1 = __float22half2_rn(make_float2(acc.z, acc.w));
        *(__half2*)&g_ninh[(size_t)n * HID + 4 * lane]     = h0;
        *(__half2*)&g_ninh[(size_t)n * HID + 4 * lane + 2] = h1;
    }
}

// ---------------- edge aggregation ----------------
__device__ __forceinline__ float4 load_h16(const __half* base, size_t row, int lane) {
    uint2 raw = *(const uint2*)(base + row * HID + lane * 4);
    float2 fa = __half22float2(*(__half2*)&raw.x);
    float2 fb = __half22float2(*(__half2*)&raw.y);
    return make_float4(fa.x, fa.y, fb.x, fb.y);
}

__global__ __launch_bounds__(256) void k_edge_agg(int layer, const float* __restrict__ t_arr)
{
    int lane = threadIdx.x & 31;
    int n = (blockIdx.x * 256 + threadIdx.x) >> 5;
    if (n >= NN) return;
    const float4* x4 = (const float4*)((layer == 0) ? g_h : g_nin);
    float tv = t_arr[layer];
    int p = g_rowptr[n], end = g_rowptr[n + 1];
    float4 sa = make_float4(0.f, 0.f, 0.f, 0.f), wa = sa;
    float4 sb = sa, wb = sa;
    for (; p + 4 <= end; p += 4) {
        int s0 = g_srcs[p], s1 = g_srcs[p + 1], s2 = g_srcs[p + 2], s3 = g_srcs[p + 3];
        float4 e0 = load_h16(g_eah, p, lane);
        float4 e1 = load_h16(g_eah, p + 1, lane);
        float4 e2 = load_h16(g_eah, p + 2, lane);
        float4 e3 = load_h16(g_eah, p + 3, lane);
        float4 h0 = load_h16(g_ninh, s0, lane);
        float4 h1 = load_h16(g_ninh, s1, lane);
        float4 h2 = load_h16(g_ninh, s2, lane);
        float4 h3 = load_h16(g_ninh, s3, lane);
#define DO_EDGE(hh, ee, S, W) { \
        float m0 = fmaxf(hh.x + ee.x, 0.f) + 1e-7f; \
        float m1 = fmaxf(hh.y + ee.y, 0.f) + 1e-7f; \
        float m2 = fmaxf(hh.z + ee.z, 0.f) + 1e-7f; \
        float m3 = fmaxf(hh.w + ee.w, 0.f) + 1e-7f; \
        float x0 = __expf(m0 * tv), x1 = __expf(m1 * tv); \
        float x2 = __expf(m2 * tv), x3 = __expf(m3 * tv); \
        S.x += x0; S.y += x1; S.z += x2; S.w += x3; \
        W.x = fmaf(m0, x0, W.x); W.y = fmaf(m1, x1, W.y); \
        W.z = fmaf(m2, x2, W.z); W.w = fmaf(m3, x3, W.w); }
        DO_EDGE(h0, e0, sa, wa);
        DO_EDGE(h1, e1, sb, wb);
        DO_EDGE(h2, e2, sa, wa);
        DO_EDGE(h3, e3, sb, wb);
    }
    for (; p < end; p++) {
        int s0 = g_srcs[p];
        float4 e0 = load_h16(g_eah, p, lane);
        float4 h0 = load_h16(g_ninh, s0, lane);
        DO_EDGE(h0, e0, sa, wa);
    }
#undef DO_EDGE
    sa.x += sb.x; sa.y += sb.y; sa.z += sb.z; sa.w += sb.w;
    wa.x += wb.x; wa.y += wb.y; wa.z += wb.z; wa.w += wb.w;
    float4 xr = x4[n * 32 + lane];
    float z[4];
    z[0] = wa.x / (sa.x + 1e-16f) + xr.x;
    z[1] = wa.y / (sa.y + 1e-16f) + xr.y;
    z[2] = wa.z / (sa.z + 1e-16f) + xr.z;
    z[3] = wa.w / (sa.w + 1e-16f) + xr.w;
    ushort hh[4], ll[4];
#pragma unroll
    for (int i = 0; i < 4; i++) {
        __nv_bfloat16 hi = __float2bfloat16(z[i]);
        __nv_bfloat16 lo = __float2bfloat16(z[i] - __bfloat162float(hi));
        hh[i] = __bfloat16_as_ushort(hi);
        ll[i] = __bfloat16_as_ushort(lo);
    }
    uint2 ph, pl;
    ph.x = (uint32_t)hh[0] | ((uint32_t)hh[1] << 16);
    ph.y = (uint32_t)hh[2] | ((uint32_t)hh[3] << 16);
    pl.x = (uint32_t)ll[0] | ((uint32_t)ll[1] << 16);
    pl.y = (uint32_t)ll[2] | ((uint32_t)ll[3] << 16);
    *(uint2*)&g_zh[(size_t)n * HID + 4 * lane] = ph;
    *(uint2*)&g_zl[(size_t)n * HID + 4 * lane] = pl;
}

// ---------------- GEMM1 (wmma): mid = relu(LN(z @ W1 + b1)), tile 64x256 ----------------
// dyn smem: sAh[64][136] bf16 (17408 B) | sAl (17408 B) | sC[64][264] f32 (67584 B) | stats 512 B
#define G1_SMEM (17408 * 2 + 67584 + 512)
__global__ __launch_bounds__(256) void k_wgemm1(
    int layer, const float* __restrict__ b1,
    const float* __restrict__ lg, const float* __restrict__ lb)
{
    extern __shared__ char smem[];
    __nv_bfloat16* sAh = (__nv_bfloat16*)smem;
    __nv_bfloat16* sAl = (__nv_bfloat16*)(smem + 17408);
    float* sC = (float*)(smem + 34816);
    float* sStat = (float*)(smem + 34816 + 67584);
    __shared__ float sB[256], sG[256], sBt[256];
    int tid = threadIdx.x;
    int n0 = blockIdx.x * 64;
    if (tid < 256) { sB[tid] = b1[tid]; sG[tid] = lg[tid]; sBt[tid] = lb[tid]; }
    for (int u = tid; u < 64 * 32; u += 256) {
        int r = u >> 5, c4 = u & 31;
        int n = n0 + r;
        uint2 vh = make_uint2(0u, 0u), vl = vh;
        if (n < NN) {
            vh = *(const uint2*)&g_zh[(size_t)n * HID + c4 * 4];
            vl = *(const uint2*)&g_zl[(size_t)n * HID + c4 * 4];
        }
        *(uint2*)&sAh[r * 136 + c4 * 4] = vh;
        *(uint2*)&sAl[r * 136 + c4 * 4] = vl;
    }
    __syncthreads();

    int w = tid >> 5;
    int wm = w >> 2, wn = w & 3;   // warp tile: rows wm*32, cols wn*64
    wmma::fragment<wmma::accumulator, 16, 16, 16, float> c[2][4];
#pragma unroll
    for (int i = 0; i < 2; i++)
#pragma unroll
        for (int j = 0; j < 4; j++) wmma::fill_fragment(c[i][j], 0.f);
    const __nv_bfloat16* w1h = g_w1h + layer * 32768;
    const __nv_bfloat16* w1l = g_w1l + layer * 32768;
#pragma unroll
    for (int ks = 0; ks < 8; ks++) {
        wmma::fragment<wmma::matrix_a, 16, 16, 16, __nv_bfloat16, wmma::row_major> ah[2], al[2];
#pragma unroll
        for (int i = 0; i < 2; i++) {
            wmma::load_matrix_sync(ah[i], sAh + (wm * 32 + i * 16) * 136 + ks * 16, 136);
            wmma::load_matrix_sync(al[i], sAl + (wm * 32 + i * 16) * 136 + ks * 16, 136);
        }
#pragma unroll
        for (int j = 0; j < 4; j++) {
            int ncol = wn * 64 + j * 16;
            wmma::fragment<wmma::matrix_b, 16, 16, 16, __nv_bfloat16, wmma::col_major> bh, bl;
            wmma::load_matrix_sync(bh, w1h + ncol * 128 + ks * 16, 128);
            wmma::load_matrix_sync(bl, w1l + ncol * 128 + ks * 16, 128);
#pragma unroll
            for (int i = 0; i < 2; i++) {
                wmma::mma_sync(c[i][j], ah[i], bh, c[i][j]);
                wmma::mma_sync(c[i][j], al[i], bh, c[i][j]);
                wmma::mma_sync(c[i][j], ah[i], bl, c[i][j]);
            }
        }
    }
#pragma unroll
    for (int i = 0; i < 2; i++)
#pragma unroll
        for (int j = 0; j < 4; j++)
            wmma::store_matrix_sync(sC + (wm * 32 + i * 16) * 264 + wn * 64 + j * 16,
                                    c[i][j], 264, wmma::mem_row_major);
    __syncthreads();
    {
        int r = tid >> 2, q = tid & 3;
        float sum = 0.f, sq = 0.f;
#pragma unroll 8
        for (int c0 = 0; c0 < 64; c0++) {
            float v = sC[r * 264 + q * 64 + c0] + sB[q * 64 + c0];
            sum += v; sq = fmaf(v, v, sq);
        }
        sum += __shfl_xor_sync(0xffffffffu, sum, 1);
        sq  += __shfl_xor_sync(0xffffffffu, sq, 1);
        sum += __shfl_xor_sync(0xffffffffu, sum, 2);
        sq  += __shfl_xor_sync(0xffffffffu, sq, 2);
        if (q == 0) {
            float m = sum * (1.f / 256.f);
            sStat[r] = m;
            sStat[64 + r] = rsqrtf(sq * (1.f / 256.f) - m * m + 1e-5f);
        }
    }
    __syncthreads();
    for (int u = tid; u < 64 * 64; u += 256) {
        int r = u >> 6, c4 = u & 63;
        int n = n0 + r;
        if (n >= NN) continue;
        float m = sStat[r], rstd = sStat[64 + r];
        ushort hh[4], ll[4];
#pragma unroll
        for (int i = 0; i < 4; i++) {
            int cc = c4 * 4 + i;
            float v = sC[r * 264 + cc] + sB[cc];
            float o = fmaxf((v - m) * rstd * sG[cc] + sBt[cc], 0.f);
            __nv_bfloat16 hi = __float2bfloat16(o);
            __nv_bfloat16 lo = __float2bfloat16(o - __bfloat162float(hi));
            hh[i] = __bfloat16_as_ushort(hi);
            ll[i] = __bfloat16_as_ushort(lo);
        }
        uint2 vh, vl;
        vh.x = (uint32_t)hh[0] | ((uint32_t)hh[1] << 16);
        vh.y = (uint32_t)hh[2] | ((uint32_t)hh[3] << 16);
        vl.x = (uint32_t)ll[0] | ((uint32_t)ll[1] << 16);
        vl.y = (uint32_t)ll[2] | ((uint32_t)ll[3] << 16);
        *(uint2*)&g_midh[(size_t)n * 256 + c4 * 4] = vh;
        *(uint2*)&g_midl[(size_t)n * 256 + c4 * 4] = vl;
    }
}

// ---------------- GEMM2 (wmma): h = mid @ W2 + b2 (+res); fused prenorm. tile 64x128 ----------------
// dyn smem: sAh[64][264] bf16 (33792 B) | sAl (33792 B) | sC[64][136] f32 (34816 B) | stats 512 B
#define G2_SMEM (33792 * 2 + 34816 + 512)
__global__ __launch_bounds__(256) void k_wgemm2(
    int layer, const float* __restrict__ b2,
    const float* __restrict__ gn, const float* __restrict__ bn,
    int use_res, int write_pre)
{
    extern __shared__ char smem[];
    __nv_bfloat16* sAh = (__nv_bfloat16*)smem;
    __nv_bfloat16* sAl = (__nv_bfloat16*)(smem + 33792);
    float* sC = (float*)(smem + 67584);
    float* sStat = (float*)(smem + 67584 + 34816);
    __shared__ float sB[128], sG[128], sBt[128];
    int tid = threadIdx.x;
    int n0 = blockIdx.x * 64;
    if (tid < 128) { sB[tid] = b2[tid]; sG[tid] = gn[tid]; sBt[tid] = bn[tid]; }
    for (int u = tid; u < 64 * 64; u += 256) {
        int r = u >> 6, c4 = u & 63;
        int n = n0 + r;
        uint2 vh = make_uint2(0u, 0u), vl = vh;
        if (n < NN) {
            vh = *(const uint2*)&g_midh[(size_t)n * 256 + c4 * 4];
            vl = *(const uint2*)&g_midl[(size_t)n * 256 + c4 * 4];
        }
        *(uint2*)&sAh[r * 264 + c4 * 4] = vh;
        *(uint2*)&sAl[r * 264 + c4 * 4] = vl;
    }
    __syncthreads();

    int w = tid >> 5;
    int wm = w >> 2, wn = w & 3;   // warp tile: rows wm*32, cols wn*32
    wmma::fragment<wmma::accumulator, 16, 16, 16, float> c[2][2];
#pragma unroll
    for (int i = 0; i < 2; i++)
#pragma unroll
        for (int j = 0; j < 2; j++) wmma::fill_fragment(c[i][j], 0.f);
    const __nv_bfloat16* w2h = g_w2h + layer * 32768;
    const __nv_bfloat16* w2l = g_w2l + layer * 32768;
#pragma unroll
    for (int ks = 0; ks < 16; ks++) {
        wmma::fragment<wmma::matrix_a, 16, 16, 16, __nv_bfloat16, wmma::row_major> ah[2], al[2];
#pragma unroll
        for (int i = 0; i < 2; i++) {
            wmma::load_matrix_sync(ah[i], sAh + (wm * 32 + i * 16) * 264 + ks * 16, 264);
            wmma::load_matrix_sync(al[i], sAl + (wm * 32 + i * 16) * 264 + ks * 16, 264);
        }
#pragma unroll
        for (int j = 0; j < 2; j++) {
            int ncol = wn * 32 + j * 16;
            wmma::fragment<wmma::matrix_b, 16, 16, 16, __nv_bfloat16, wmma::col_major> bh, bl;
            wmma::load_matrix_sync(bh, w2h + ncol * 256 + ks * 16, 256);
            wmma::load_matrix_sync(bl, w2l + ncol * 256 + ks * 16, 256);
#pragma unroll
            for (int i = 0; i < 2; i++) {
                wmma::mma_sync(c[i][j], ah[i], bh, c[i][j]);
                wmma::mma_sync(c[i][j], al[i], bh, c[i][j]);
                wmma::mma_sync(c[i][j], ah[i], bl, c[i][j]);
            }
        }
    }
#pragma unroll
    for (int i = 0; i < 2; i++)
#pragma unroll
        for (int j = 0; j < 2; j++)
            wmma::store_matrix_sync(sC + (wm * 32 + i * 16) * 136 + wn * 32 + j * 16,
                                    c[i][j], 136, wmma::mem_row_major);
    __syncthreads();
    // bias + residual into sC
    for (int u = tid; u < 64 * 32; u += 256) {
        int r = u >> 5, c4 = u & 31;
        int n = n0 + r;
        float4 res = make_float4(0.f, 0.f, 0.f, 0.f);
        if (use_res && n < NN) res = *(const float4*)&g_h[n * HID + c4 * 4];
#pragma unroll
        for (int i = 0; i < 4; i++) {
            int cc = c4 * 4 + i;
            sC[r * 136 + cc] += sB[cc] + ((const float*)&res)[i];
        }
    }
    __syncthreads();
    {
        int r = tid >> 2, q = tid & 3;
        float sum = 0.f, sq = 0.f;
#pragma unroll 8
        for (int c0 = 0; c0 < 32; c0++) {
            float v = sC[r * 136 + q * 32 + c0];
            sum += v; sq = fmaf(v, v, sq);
        }
        sum += __shfl_xor_sync(0xffffffffu, sum, 1);
        sq  += __shfl_xor_sync(0xffffffffu, sq, 1);
        sum += __shfl_xor_sync(0xffffffffu, sum, 2);
        sq  += __shfl_xor_sync(0xffffffffu, sq, 2);
        if (q == 0) {
            float m = sum * (1.f / 128.f);
            sStat[r] = m;
            sStat[64 + r] = rsqrtf(sq * (1.f / 128.f) - m * m + 1e-5f);
        }
    }
    __syncthreads();
    for (int u = tid; u < 64 * 32; u += 256) {
        int r = u >> 5, c4 = u & 31;
        int n = n0 + r;
        if (n >= NN) continue;
        float4 v;
        v.x = sC[r * 136 + c4 * 4 + 0];
        v.y = sC[r * 136 + c4 * 4 + 1];
        v.z = sC[r * 136 + c4 * 4 + 2];
        v.w = sC[r * 136 + c4 * 4 + 3];
        *(float4*)&g_h[n * HID + c4 * 4] = v;
        if (write_pre) {
            float m = sStat[r], rstd = sStat[64 + r];
            float4 o;
            o.x = fmaxf((v.x - m) * rstd * sG[c4 * 4 + 0] + sBt[c4 * 4 + 0], 0.f);
            o.y = fmaxf((v.y - m) * rstd * sG[c4 * 4 + 1] + sBt[c4 * 4 + 1], 0.f);
            o.z = fmaxf((v.z - m) * rstd * sG[c4 * 4 + 2] + sBt[c4 * 4 + 2], 0.f);
            o.w = fmaxf((v.w - m) * rstd * sG[c4 * 4 + 3] + sBt[c4 * 4 + 3], 0.f);
            *(float4*)&g_nin[n * HID + c4 * 4] = o;
            uint2 hp;
            __half2 ha = __float22half2_rn(make_float2(o.x, o.y));
            __half2 hb = __float22half2_rn(make_float2(o.z, o.w));
            hp.x = *(uint32_t*)&ha; hp.y = *(uint32_t*)&hb;
            *(uint2*)&g_ninh[(size_t)n * HID + c4 * 4] = hp;
        }
    }
}

// ---------------- classifier ----------------
__global__ __launch_bounds__(256) void k_classifier(
    const float* __restrict__ gmm, const float* __restrict__ bb,
    const float* __restrict__ lw, const float* __restrict__ lbias,
    float* __restrict__ out)
{
    int lane = threadIdx.x & 31;
    int n = (blockIdx.x * 256 + threadIdx.x) >> 5;
    if (n >= NN) return;
    float4 v = ((const float4*)g_h)[n * 32 + lane];
    float s = v.x + v.y + v.z + v.w;
    float q = v.x * v.x + v.y * v.y + v.z * v.z + v.w * v.w;
#pragma unroll
    for (int off = 16; off; off >>= 1) {
        s += __shfl_xor_sync(0xffffffffu, s, off);
        q += __shfl_xor_sync(0xffffffffu, q, off);
    }
    float m = s * (1.f / 128.f);
    float var = q * (1.f / 128.f) - m * m;
    float rstd = rsqrtf(var + 1e-5f);
    float4 g4 = ((const float4*)gmm)[lane];
    float4 b4 = ((const float4*)bb)[lane];
    float h0 = fmaxf((v.x - m) * rstd * g4.x + b4.x, 0.f);
    float h1 = fmaxf((v.y - m) * rstd * g4.y + b4.y, 0.f);
    float h2 = fmaxf((v.z - m) * rstd * g4.z + b4.z, 0.f);
    float h3 = fmaxf((v.w - m) * rstd * g4.w + b4.w, 0.f);
    int c0 = lane * 4;
    float r[NCLS];
#pragma unroll
    for (int j = 0; j < NCLS; j++) {
        float p = h0 * lw[c0 * NCLS + j];
        p = fmaf(h1, lw[(c0 + 1) * NCLS + j], p);
        p = fmaf(h2, lw[(c0 + 2) * NCLS + j], p);
        p = fmaf(h3, lw[(c0 + 3) * NCLS + j], p);
#pragma unroll
        for (int off = 16; off; off >>= 1) p += __shfl_xor_sync(0xffffffffu, p, off);
        r[j] = p;
    }
#pragma unroll
    for (int j = 0; j < NCLS; j++)
        if (lane == j) out[n * NCLS + j] = r[j] + lbias[j];
}

// ---------------- launch ----------------
extern "C" void kernel_launch(void* const* d_in, const int* in_sizes, int n_in,
                              void* d_out, int out_size)
{
    const float* x         = (const float*)d_in[0];
    const float* edge_attr = (const float*)d_in[1];
    const float* node_w    = (const float*)d_in[2];
    const float* node_b    = (const float*)d_in[3];
    const float* edge_w    = (const float*)d_in[4];
    const float* edge_b    = (const float*)d_in[5];
    const float* mlp1_w    = (const float*)d_in[6];
    const float* mlp1_b    = (const float*)d_in[7];
    const float* ln_g      = (const float*)d_in[8];
    const float* ln_b      = (const float*)d_in[9];
    const float* mlp2_w    = (const float*)d_in[10];
    const float* mlp2_b    = (const float*)d_in[11];
    const float* t         = (const float*)d_in[12];
    const float* norm_g    = (const float*)d_in[13];
    const float* norm_b    = (const float*)d_in[14];
    const float* lin_w     = (const float*)d_in[15];
    const float* lin_b     = (const float*)d_in[16];
    const int*   edge_index= (const int*)d_in[17];
    const int* src = edge_index;
    const int* dst = edge_index + NE;
    float* out = (float*)d_out;

    static int attr_done = 0;
    if (!attr_done) {
        cudaFuncSetAttribute(k_wgemm1, cudaFuncAttributeMaxDynamicSharedMemorySize, G1_SMEM);
        cudaFuncSetAttribute(k_wgemm2, cudaFuncAttributeMaxDynamicSharedMemorySize, G2_SMEM);
        attr_done = 1;
    }

    // g_cnt is zero on entry (module-load zero; trailing k_zero_cnt each replay)
    k_node_enc<<<1184, 256>>>(x, node_w, node_b);                          // 0
    k_hist<<<(NE + 255) / 256, 256>>>(dst);                                // 1
    k_scan<<<1, 1024>>>();                                                 // 2
    k_encscatter<<<NE / 128, 256>>>(edge_attr, src, dst, edge_w, edge_b);  // 3 <- profiled
    k_wconv<<<384, 256>>>(mlp1_w, mlp2_w);                                 // 4

    const int GGRID = (NN + 63) / 64;   // 469
    for (int l = 0; l < 3; l++) {
        k_edge_agg<<<(NN * 32 + 255) / 256, 256>>>(l, t);
        k_wgemm1<<<GGRID, 256, G1_SMEM>>>(l, mlp1_b + l * 256,
                                          ln_g + l * 256, ln_b + l * 256);
        k_wgemm2<<<GGRID, 256, G2_SMEM>>>(l, mlp2_b + l * HID,
                                          norm_g + (l + 1) * HID, norm_b + (l + 1) * HID,
                                          l > 0, l < 2 ? 1 : 0);
    }
    k_classifier<<<(NN * 32 + 255) / 256, 256>>>(norm_g, norm_b, lin_w, lin_b, out);
    k_zero_cnt<<<(NN + 255) / 256, 256>>>();
}